// round 10
// baseline (speedup 1.0000x reference)
#include <cuda_runtime.h>
#include <cuda_fp16.h>
#include <math.h>
#include <stdint.h>

#define NN 50000
#define EE 800000
#define E2 (EE + NN)
#define NB ((NN + 255) / 256)
#define BN_EPS 1e-5f

// ---------------- scratch (static __device__, no allocations) ----------------
__device__ int    g_is64;
__device__ int    g_src[EE];
__device__ int    g_dst[EE];
__device__ int    g_deg[NN];
__device__ int    g_bsum[256];
__device__ int    g_boff[256];
__device__ int    g_rowptr[NN + 1];
__device__ int    g_fill[NN];
__device__ int    g_colsrc[E2];
__device__ float  g_dinv[NN];
__device__ float  g_bufA[NN * 64];
__device__ float  g_bufB[NN * 64];
__device__ __half g_hbuf[(size_t)NN * 512];   // 51.2 MB fp16 feature buffer
__device__ float  g_es[NN * 8];
__device__ float  g_ed[NN * 8];

// ---------------- helpers ----------------
__device__ __forceinline__ float warp_max(float v) {
    #pragma unroll
    for (int o = 16; o; o >>= 1) v = fmaxf(v, __shfl_xor_sync(0xffffffffu, v, o));
    return v;
}
__device__ __forceinline__ float warp_sum(float v) {
    #pragma unroll
    for (int o = 16; o; o >>= 1) v += __shfl_xor_sync(0xffffffffu, v, o);
    return v;
}
__device__ __forceinline__ float lrelu(float x) { return x > 0.f ? x : 0.2f * x; }

// ---------------- graph-structure kernels ----------------
__global__ void detect_kernel(const int* __restrict__ ei) {
    int l = threadIdx.x;
    int any = 0;
    #pragma unroll
    for (int j = 0; j < 32; j++) any |= ei[2 * (j * 32 + l) + 1];
    #pragma unroll
    for (int o = 16; o; o >>= 1) any |= __shfl_xor_sync(0xffffffffu, any, o);
    if (l == 0) g_is64 = (any == 0) ? 1 : 0;
}

__global__ void convert_count_kernel(const void* __restrict__ ei) {
    int e = blockIdx.x * blockDim.x + threadIdx.x;
    if (e >= EE) return;
    int s, d;
    if (g_is64) {
        const long long* p = (const long long*)ei;
        s = (int)p[e];
        d = (int)p[EE + e];
    } else {
        const int* p = (const int*)ei;
        s = p[e];
        d = p[EE + e];
    }
    g_src[e] = s;
    g_dst[e] = d;
    atomicAdd(&g_deg[d], 1);
}

__global__ __launch_bounds__(256) void bsum_kernel() {
    __shared__ int sh[256];
    int t = threadIdx.x;
    int n = blockIdx.x * 256 + t;
    int v = (n < NN) ? (g_deg[n] + 1) : 0;
    sh[t] = v;
    __syncthreads();
    #pragma unroll
    for (int o = 128; o; o >>= 1) {
        if (t < o) sh[t] += sh[t + o];
        __syncthreads();
    }
    if (t == 0) g_bsum[blockIdx.x] = sh[0];
}

__global__ __launch_bounds__(256) void bscan_kernel() {
    __shared__ int sh[256];
    int t = threadIdx.x;
    int v = (t < NB) ? g_bsum[t] : 0;
    sh[t] = v;
    __syncthreads();
    #pragma unroll
    for (int o = 1; o < 256; o <<= 1) {
        int u = (t >= o) ? sh[t - o] : 0;
        __syncthreads();
        sh[t] += u;
        __syncthreads();
    }
    g_boff[t] = sh[t] - v;
}

__global__ __launch_bounds__(256) void rowptr_kernel() {
    __shared__ int sh[256];
    int t = threadIdx.x;
    int n = blockIdx.x * 256 + t;
    int v = (n < NN) ? (g_deg[n] + 1) : 0;
    sh[t] = v;
    __syncthreads();
    #pragma unroll
    for (int o = 1; o < 256; o <<= 1) {
        int u = (t >= o) ? sh[t - o] : 0;
        __syncthreads();
        sh[t] += u;
        __syncthreads();
    }
    int excl = sh[t] - v + g_boff[blockIdx.x];
    if (n < NN) {
        g_rowptr[n] = excl;
        g_fill[n]   = excl;
        g_dinv[n]   = rsqrtf((float)v);
    }
    if (n == NN - 1) g_rowptr[NN] = excl + v;
}

__global__ void fill_kernel() {
    int idx = blockIdx.x * blockDim.x + threadIdx.x;
    if (idx >= E2) return;
    int s, d;
    if (idx < EE) { s = g_src[idx]; d = g_dst[idx]; }
    else          { s = d = idx - EE; }
    int pos = atomicAdd(&g_fill[d], 1);
    g_colsrc[pos] = s;
}

__global__ void sort_kernel() {
    int r = blockIdx.x * blockDim.x + threadIdx.x;
    if (r >= NN) return;
    int s0 = g_rowptr[r], s1 = g_rowptr[r + 1];
    for (int i = s0 + 1; i < s1; i++) {
        int v = g_colsrc[i];
        int j = i - 1;
        while (j >= s0 && g_colsrc[j] > v) { g_colsrc[j + 1] = g_colsrc[j]; j--; }
        g_colsrc[j + 1] = v;
    }
}

// ---------------- tensor-core GEMM: Y(fp16)[M,NO] = X(fp32)[M,K] @ W[K,NO] ---
template <int K, int NO>
__global__ __launch_bounds__(256) void tc_gemm_kernel(const float* __restrict__ X,
                                                      const float* __restrict__ W,
                                                      __half* __restrict__ Y) {
    __shared__ __half As[128][72];
    __shared__ __half Bs[64][72];
    int t = threadIdx.x;
    int lane = t & 31, wid = t >> 5;
    int warp_m = wid & 3, warp_n = wid >> 2;
    int rowBase = blockIdx.x * 128;
    int colBase = blockIdx.y * 64;

    float c[2][4][4];
    #pragma unroll
    for (int mt = 0; mt < 2; mt++)
        #pragma unroll
        for (int nt = 0; nt < 4; nt++)
            #pragma unroll
            for (int i = 0; i < 4; i++) c[mt][nt][i] = 0.f;

    for (int kc = 0; kc < K; kc += 64) {
        if (kc) __syncthreads();
        #pragma unroll
        for (int i = 0; i < 8; i++) {
            int idx = i * 256 + t;
            int r = idx >> 4, g = idx & 15;
            int row = rowBase + r;
            float4 f = (row < NN)
                ? *(const float4*)(X + (size_t)row * K + kc + g * 4)
                : make_float4(0.f, 0.f, 0.f, 0.f);
            *(__half2*)&As[r][g * 4]     = __floats2half2_rn(f.x, f.y);
            *(__half2*)&As[r][g * 4 + 2] = __floats2half2_rn(f.z, f.w);
        }
        #pragma unroll
        for (int i = 0; i < 4; i++) {
            int idx = i * 256 + t;
            int k = idx >> 4, g = idx & 15;
            float4 f = *(const float4*)(W + (size_t)(kc + k) * NO + colBase + g * 4);
            *(__half2*)&Bs[k][g * 4]     = __floats2half2_rn(f.x, f.y);
            *(__half2*)&Bs[k][g * 4 + 2] = __floats2half2_rn(f.z, f.w);
        }
        __syncthreads();
        #pragma unroll
        for (int ks = 0; ks < 4; ks++) {
            uint32_t a[2][4], b[2][4];
            #pragma unroll
            for (int mt = 0; mt < 2; mt++) {
                const __half* p = &As[warp_m * 32 + mt * 16 + (lane & 15)][ks * 16 + (lane >> 4) * 8];
                uint32_t addr = (uint32_t)__cvta_generic_to_shared(p);
                asm volatile("ldmatrix.sync.aligned.m8n8.x4.shared.b16 {%0,%1,%2,%3}, [%4];"
                    : "=r"(a[mt][0]), "=r"(a[mt][1]), "=r"(a[mt][2]), "=r"(a[mt][3])
                    : "r"(addr));
            }
            #pragma unroll
            for (int ng = 0; ng < 2; ng++) {
                const __half* p = &Bs[ks * 16 + (lane & 15)][warp_n * 32 + ng * 16 + (lane >> 4) * 8];
                uint32_t addr = (uint32_t)__cvta_generic_to_shared(p);
                asm volatile("ldmatrix.sync.aligned.m8n8.x4.trans.shared.b16 {%0,%1,%2,%3}, [%4];"
                    : "=r"(b[ng][0]), "=r"(b[ng][1]), "=r"(b[ng][2]), "=r"(b[ng][3])
                    : "r"(addr));
            }
            #pragma unroll
            for (int mt = 0; mt < 2; mt++)
                #pragma unroll
                for (int nt = 0; nt < 4; nt++) {
                    uint32_t b0 = b[nt >> 1][(nt & 1) * 2];
                    uint32_t b1 = b[nt >> 1][(nt & 1) * 2 + 1];
                    asm volatile(
                        "mma.sync.aligned.m16n8k16.row.col.f32.f16.f16.f32 "
                        "{%0,%1,%2,%3}, {%4,%5,%6,%7}, {%8,%9}, {%0,%1,%2,%3};"
                        : "+f"(c[mt][nt][0]), "+f"(c[mt][nt][1]),
                          "+f"(c[mt][nt][2]), "+f"(c[mt][nt][3])
                        : "r"(a[mt][0]), "r"(a[mt][1]), "r"(a[mt][2]), "r"(a[mt][3]),
                          "r"(b0), "r"(b1));
                }
        }
    }
    #pragma unroll
    for (int mt = 0; mt < 2; mt++) {
        int r0 = rowBase + warp_m * 32 + mt * 16 + (lane >> 2);
        #pragma unroll
        for (int nt = 0; nt < 4; nt++) {
            int col = colBase + warp_n * 32 + nt * 8 + (lane & 3) * 2;
            if (r0 < NN)
                *(__half2*)(Y + (size_t)r0 * NO + col) = __floats2half2_rn(c[mt][nt][0], c[mt][nt][1]);
            if (r0 + 8 < NN)
                *(__half2*)(Y + (size_t)(r0 + 8) * NO + col) = __floats2half2_rn(c[mt][nt][2], c[mt][nt][3]);
        }
    }
}

// ---------------- GAT attention coefficients from fp16 features -------------
template <int CH>
__global__ __launch_bounds__(256) void esed_kernel(const __half* __restrict__ hb,
                                                   const float* __restrict__ asrc,
                                                   const float* __restrict__ adst,
                                                   float* __restrict__ es,
                                                   float* __restrict__ ed) {
    int wid = (blockIdx.x * blockDim.x + threadIdx.x) >> 5;
    int l   = threadIdx.x & 31;
    if (wid >= NN * 8) return;
    int n = wid >> 3, hh = wid & 7;
    const __half* hp = hb + (size_t)n * (8 * CH) + hh * CH;
    const float* as = asrc + hh * CH;
    const float* ad = adst + hh * CH;
    float s, d;
    if (CH == 64) {
        float2 v = __half22float2(*(const __half2*)(hp + 2 * l));
        s = v.x * as[2 * l] + v.y * as[2 * l + 1];
        d = v.x * ad[2 * l] + v.y * ad[2 * l + 1];
    } else {
        float v = __half2float(hp[l]);
        s = v * as[l];
        d = v * ad[l];
    }
    s = warp_sum(s);
    d = warp_sum(d);
    if (l == 0) { es[n * 8 + hh] = s; ed[n * 8 + hh] = d; }
}

// ---------------- GCN aggregation (fp16 in, batch-2) + BN(eval) + ReLU ------
__global__ __launch_bounds__(256) void gcn_agg_kernel(const __half* __restrict__ h,
                                                      const float* __restrict__ bias,
                                                      const float* __restrict__ gamma,
                                                      const float* __restrict__ beta,
                                                      const float* __restrict__ mean,
                                                      const float* __restrict__ var,
                                                      float* __restrict__ out) {
    int w = (blockIdx.x * blockDim.x + threadIdx.x) >> 5;
    int l = threadIdx.x & 31;
    if (w >= NN) return;
    int s0 = g_rowptr[w], s1 = g_rowptr[w + 1];
    float a0 = 0.f, a1 = 0.f;
    const __half2* hb = (const __half2*)h;
    for (int i = s0; i < s1; i += 2) {
        int sA = g_colsrc[i];
        int sB = (i + 1 < s1) ? g_colsrc[i + 1] : sA;
        float dvA = g_dinv[sA];
        float dvB = (i + 1 < s1) ? g_dinv[sB] : 0.f;
        __half2 hA = hb[sA * 32 + l];
        __half2 hB = hb[sB * 32 + l];
        float2 vA = __half22float2(hA);
        float2 vB = __half22float2(hB);
        a0 += dvA * vA.x;
        a1 += dvA * vA.y;
        a0 += dvB * vB.x;
        a1 += dvB * vB.y;
    }
    float dd = g_dinv[w];
    float2 bi = ((const float2*)bias)[l];
    float2 me = ((const float2*)mean)[l];
    float2 va = ((const float2*)var)[l];
    float2 ga = ((const float2*)gamma)[l];
    float2 be = ((const float2*)beta)[l];
    float v0 = a0 * dd + bi.x;
    float v1 = a1 * dd + bi.y;
    v0 = (v0 - me.x) * rsqrtf(va.x + BN_EPS) * ga.x + be.x;
    v1 = (v1 - me.y) * rsqrtf(va.y + BN_EPS) * ga.y + be.y;
    ((float2*)(out + (size_t)w * 64))[l] = make_float2(fmaxf(v0, 0.f), fmaxf(v1, 0.f));
}

// ---------------- GAT aggregation: max pass + batched fused den/sum pass ----
template <int CH, int RELU, int LOGSM>
__global__ __launch_bounds__(256) void gat_agg_kernel(const __half* __restrict__ hb,
                                                      const float* __restrict__ es,
                                                      const float* __restrict__ ed,
                                                      const float* __restrict__ bias,
                                                      float* __restrict__ out) {
    int d = (blockIdx.x * blockDim.x + threadIdx.x) >> 5;
    int l = threadIdx.x & 31;
    if (d >= NN) return;
    int s0 = g_rowptr[d], s1 = g_rowptr[d + 1];

    float edv[8];
    {
        const float4* e4 = (const float4*)(ed + d * 8);
        float4 a = e4[0], b = e4[1];
        edv[0] = a.x; edv[1] = a.y; edv[2] = a.z; edv[3] = a.w;
        edv[4] = b.x; edv[5] = b.y; edv[6] = b.z; edv[7] = b.w;
    }

    // pass 1: per-head max (lane-strided; order-independent)
    float m[8];
    #pragma unroll
    for (int h = 0; h < 8; h++) m[h] = -1e30f;
    for (int i = s0 + l; i < s1; i += 32) {
        int s = g_colsrc[i];
        const float4* e4 = (const float4*)(es + s * 8);
        float4 a = e4[0], b = e4[1];
        float ev[8] = {a.x, a.y, a.z, a.w, b.x, b.y, b.z, b.w};
        #pragma unroll
        for (int h = 0; h < 8; h++) m[h] = fmaxf(m[h], lrelu(ev[h] + edv[h]));
    }
    #pragma unroll
    for (int h = 0; h < 8; h++) m[h] = warp_max(m[h]);

    // pass 2 (fused, batch=2, feature preload): unnormalized weights +
    // weighted feature sums. Lanes 0..7 compute w for head==lane; fixed
    // accumulation order -> deterministic. Tail edge uses weight 0.
    float den = 0.f;
    float acc0[8], acc1[8];
    #pragma unroll
    for (int h = 0; h < 8; h++) { acc0[h] = 0.f; acc1[h] = 0.f; }

    for (int i = s0; i < s1; i += 2) {
        bool two = (i + 1 < s1);
        int sA = g_colsrc[i];
        int sB = two ? g_colsrc[i + 1] : sA;
        float wA = 0.f, wB = 0.f;
        if (l < 8) {
            wA = expf(lrelu(es[sA * 8 + l] + edv[l]) - m[l]);
            if (two) wB = expf(lrelu(es[sB * 8 + l] + edv[l]) - m[l]);
        }
        den += wA + wB;
        if (CH == 64) {
            const __half2* pA = (const __half2*)(hb + (size_t)sA * 512);
            const __half2* pB = (const __half2*)(hb + (size_t)sB * 512);
            __half2 vA[8], vB[8];
            #pragma unroll
            for (int h = 0; h < 8; h++) { vA[h] = pA[h * 32 + l]; vB[h] = pB[h * 32 + l]; }
            #pragma unroll
            for (int h = 0; h < 8; h++) {
                float whA = __shfl_sync(0xffffffffu, wA, h);
                float2 f = __half22float2(vA[h]);
                acc0[h] += whA * f.x;
                acc1[h] += whA * f.y;
            }
            #pragma unroll
            for (int h = 0; h < 8; h++) {
                float whB = __shfl_sync(0xffffffffu, wB, h);
                float2 f = __half22float2(vB[h]);
                acc0[h] += whB * f.x;
                acc1[h] += whB * f.y;
            }
        } else {
            const __half* pA = hb + (size_t)sA * 256;
            const __half* pB = hb + (size_t)sB * 256;
            __half vA[8], vB[8];
            #pragma unroll
            for (int h = 0; h < 8; h++) { vA[h] = pA[h * 32 + l]; vB[h] = pB[h * 32 + l]; }
            #pragma unroll
            for (int h = 0; h < 8; h++) {
                float whA = __shfl_sync(0xffffffffu, wA, h);
                acc0[h] += whA * __half2float(vA[h]);
            }
            #pragma unroll
            for (int h = 0; h < 8; h++) {
                float whB = __shfl_sync(0xffffffffu, wB, h);
                acc0[h] += whB * __half2float(vB[h]);
            }
        }
    }

    float v0 = 0.f, v1 = 0.f;
    #pragma unroll
    for (int h = 0; h < 8; h++) {
        float rd = 1.f / (__shfl_sync(0xffffffffu, den, h) + 1e-16f);
        v0 += acc0[h] * rd;
        if (CH == 64) v1 += acc1[h] * rd;
    }

    if (CH == 64) {
        float2 bi = ((const float2*)bias)[l];
        v0 = v0 * 0.125f + bi.x;
        v1 = v1 * 0.125f + bi.y;
        if (RELU) { v0 = fmaxf(v0, 0.f); v1 = fmaxf(v1, 0.f); }
        ((float2*)(out + (size_t)d * 64))[l] = make_float2(v0, v1);
    } else {
        v0 = v0 * 0.125f + bias[l];
        if (RELU) v0 = fmaxf(v0, 0.f);
        if (LOGSM) {
            float mx = warp_max(v0);
            float se = warp_sum(expf(v0 - mx));
            v0 = v0 - mx - logf(se);
        }
        out[(size_t)d * 32 + l] = v0;
    }
}

// ---------------- launch ----------------
extern "C" void kernel_launch(void* const* d_in, const int* in_sizes, int n_in,
                              void* d_out, int out_size) {
    const float* X        = (const float*)d_in[0];
    const void*  EI       = d_in[1];
    const float* gcn1_w   = (const float*)d_in[2];
    const float* gcn1_b   = (const float*)d_in[3];
    const float* bn1_g    = (const float*)d_in[4];
    const float* bn1_be   = (const float*)d_in[5];
    const float* bn1_m    = (const float*)d_in[6];
    const float* bn1_v    = (const float*)d_in[7];
    const float* gat1_w   = (const float*)d_in[8];
    const float* gat1_as  = (const float*)d_in[9];
    const float* gat1_ad  = (const float*)d_in[10];
    const float* gat1_b   = (const float*)d_in[11];
    const float* gcn2_w   = (const float*)d_in[12];
    const float* gcn2_b   = (const float*)d_in[13];
    const float* bn2_g    = (const float*)d_in[14];
    const float* bn2_be   = (const float*)d_in[15];
    const float* bn2_m    = (const float*)d_in[16];
    const float* bn2_v    = (const float*)d_in[17];
    const float* gat2_w   = (const float*)d_in[18];
    const float* gat2_as  = (const float*)d_in[19];
    const float* gat2_ad  = (const float*)d_in[20];
    const float* gat2_b   = (const float*)d_in[21];
    float* OUT = (float*)d_out;

    float *bufA, *bufB, *es, *ed;
    __half* hbuf;
    int* degPtr;
    cudaGetSymbolAddress((void**)&bufA,   g_bufA);
    cudaGetSymbolAddress((void**)&bufB,   g_bufB);
    cudaGetSymbolAddress((void**)&hbuf,   g_hbuf);
    cudaGetSymbolAddress((void**)&es,     g_es);
    cudaGetSymbolAddress((void**)&ed,     g_ed);
    cudaGetSymbolAddress((void**)&degPtr, g_deg);

    const int TB = 256;
    int gRows      = (NN + 127) / 128;   // 391
    int aggBlocks  = (NN * 32 + TB - 1) / TB;
    int esedBlocks = (NN * 8 * 32 + TB - 1) / TB;

    // graph build, with tc_gemm1 placed 5th so ncu (-s 5) captures it.
    detect_kernel<<<1, 32>>>((const int*)EI);                 // 1
    cudaMemsetAsync(degPtr, 0, NN * sizeof(int));             // 2
    convert_count_kernel<<<(EE + TB - 1) / TB, TB>>>(EI);     // 3
    bsum_kernel<<<NB, 256>>>();                               // 4
    tc_gemm_kernel<128, 64><<<dim3(gRows, 1), TB>>>(X, gcn1_w, hbuf);  // 5 <- profiled
    bscan_kernel<<<1, 256>>>();
    rowptr_kernel<<<NB, 256>>>();
    fill_kernel<<<(E2 + TB - 1) / TB, TB>>>();
    sort_kernel<<<(NN + TB - 1) / TB, TB>>>();

    // layer 1: GCN -> BN -> ReLU
    gcn_agg_kernel<<<aggBlocks, TB>>>(hbuf, gcn1_b, bn1_g, bn1_be, bn1_m, bn1_v, bufB);

    // layer 2: GAT(8 heads, 64 ch, mean) -> ReLU
    tc_gemm_kernel<64, 512><<<dim3(gRows, 8), TB>>>(bufB, gat1_w, hbuf);
    esed_kernel<64><<<esedBlocks, TB>>>(hbuf, gat1_as, gat1_ad, es, ed);
    gat_agg_kernel<64, 1, 0><<<aggBlocks, TB>>>(hbuf, es, ed, gat1_b, bufA);

    // layer 3: GCN -> BN -> ReLU
    tc_gemm_kernel<64, 64><<<dim3(gRows, 1), TB>>>(bufA, gcn2_w, hbuf);
    gcn_agg_kernel<<<aggBlocks, TB>>>(hbuf, gcn2_b, bn2_g, bn2_be, bn2_m, bn2_v, bufB);

    // layer 4: GAT(8 heads, 32 ch, mean) + log_softmax
    tc_gemm_kernel<64, 256><<<dim3(gRows, 4), TB>>>(bufB, gat2_w, hbuf);
    esed_kernel<32><<<esedBlocks, TB>>>(hbuf, gat2_as, gat2_ad, es, ed);
    gat_agg_kernel<32, 0, 1><<<aggBlocks, TB>>>(hbuf, es, ed, gat2_b, OUT);
}

// round 12
// speedup vs baseline: 1.1403x; 1.1403x over previous
#include <cuda_runtime.h>
#include <cuda_fp16.h>
#include <math.h>
#include <stdint.h>

#define NN 50000
#define EE 800000
#define E2 (EE + NN)
#define NB ((NN + 255) / 256)
#define BN_EPS 1e-5f

// ---------------- scratch (static __device__, no allocations) ----------------
__device__ int    g_is64;
__device__ int    g_src[EE];
__device__ int    g_dst[EE];
__device__ int    g_deg[NN];
__device__ int    g_bsum[256];
__device__ int    g_boff[256];
__device__ int    g_rowptr[NN + 1];
__device__ int    g_fill[NN];
__device__ int    g_colsrc[E2];
__device__ float  g_dinv[NN];
__device__ float  g_bufA[NN * 64];
__device__ float  g_bufB[NN * 64];
__device__ __half g_hbuf[(size_t)NN * 512];   // 51.2 MB fp16 feature buffer
__device__ float  g_es[NN * 8];
__device__ float  g_ed[NN * 8];

// ---------------- helpers ----------------
__device__ __forceinline__ float warp_max(float v) {
    #pragma unroll
    for (int o = 16; o; o >>= 1) v = fmaxf(v, __shfl_xor_sync(0xffffffffu, v, o));
    return v;
}
__device__ __forceinline__ float warp_sum(float v) {
    #pragma unroll
    for (int o = 16; o; o >>= 1) v += __shfl_xor_sync(0xffffffffu, v, o);
    return v;
}
__device__ __forceinline__ float lrelu(float x) { return x > 0.f ? x : 0.2f * x; }

// ---------------- graph-structure kernels ----------------
__global__ void detect_kernel(const int* __restrict__ ei) {
    int l = threadIdx.x;
    int any = 0;
    #pragma unroll
    for (int j = 0; j < 32; j++) any |= ei[2 * (j * 32 + l) + 1];
    #pragma unroll
    for (int o = 16; o; o >>= 1) any |= __shfl_xor_sync(0xffffffffu, any, o);
    if (l == 0) g_is64 = (any == 0) ? 1 : 0;
}

__global__ void convert_count_kernel(const void* __restrict__ ei) {
    int e = blockIdx.x * blockDim.x + threadIdx.x;
    if (e >= EE) return;
    int s, d;
    if (g_is64) {
        const long long* p = (const long long*)ei;
        s = (int)p[e];
        d = (int)p[EE + e];
    } else {
        const int* p = (const int*)ei;
        s = p[e];
        d = p[EE + e];
    }
    g_src[e] = s;
    g_dst[e] = d;
    atomicAdd(&g_deg[d], 1);
}

__global__ __launch_bounds__(256) void bsum_kernel() {
    __shared__ int sh[256];
    int t = threadIdx.x;
    int n = blockIdx.x * 256 + t;
    int v = (n < NN) ? (g_deg[n] + 1) : 0;
    sh[t] = v;
    __syncthreads();
    #pragma unroll
    for (int o = 128; o; o >>= 1) {
        if (t < o) sh[t] += sh[t + o];
        __syncthreads();
    }
    if (t == 0) g_bsum[blockIdx.x] = sh[0];
}

__global__ __launch_bounds__(256) void bscan_kernel() {
    __shared__ int sh[256];
    int t = threadIdx.x;
    int v = (t < NB) ? g_bsum[t] : 0;
    sh[t] = v;
    __syncthreads();
    #pragma unroll
    for (int o = 1; o < 256; o <<= 1) {
        int u = (t >= o) ? sh[t - o] : 0;
        __syncthreads();
        sh[t] += u;
        __syncthreads();
    }
    g_boff[t] = sh[t] - v;
}

__global__ __launch_bounds__(256) void rowptr_kernel() {
    __shared__ int sh[256];
    int t = threadIdx.x;
    int n = blockIdx.x * 256 + t;
    int v = (n < NN) ? (g_deg[n] + 1) : 0;
    sh[t] = v;
    __syncthreads();
    #pragma unroll
    for (int o = 1; o < 256; o <<= 1) {
        int u = (t >= o) ? sh[t - o] : 0;
        __syncthreads();
        sh[t] += u;
        __syncthreads();
    }
    int excl = sh[t] - v + g_boff[blockIdx.x];
    if (n < NN) {
        g_rowptr[n] = excl;
        g_fill[n]   = excl;
        g_dinv[n]   = rsqrtf((float)v);
    }
    if (n == NN - 1) g_rowptr[NN] = excl + v;
}

__global__ void fill_kernel() {
    int idx = blockIdx.x * blockDim.x + threadIdx.x;
    if (idx >= E2) return;
    int s, d;
    if (idx < EE) { s = g_src[idx]; d = g_dst[idx]; }
    else          { s = d = idx - EE; }
    int pos = atomicAdd(&g_fill[d], 1);
    g_colsrc[pos] = s;
}

__global__ void sort_kernel() {
    int r = blockIdx.x * blockDim.x + threadIdx.x;
    if (r >= NN) return;
    int s0 = g_rowptr[r], s1 = g_rowptr[r + 1];
    for (int i = s0 + 1; i < s1; i++) {
        int v = g_colsrc[i];
        int j = i - 1;
        while (j >= s0 && g_colsrc[j] > v) { g_colsrc[j + 1] = g_colsrc[j]; j--; }
        g_colsrc[j + 1] = v;
    }
}

// ---------------- tensor-core GEMM: Y(fp16)[M,NO] = X(fp32)[M,K] @ W[K,NO] ---
template <int K, int NO>
__global__ __launch_bounds__(256) void tc_gemm_kernel(const float* __restrict__ X,
                                                      const float* __restrict__ W,
                                                      __half* __restrict__ Y) {
    __shared__ __half As[128][72];
    __shared__ __half Bs[64][72];
    int t = threadIdx.x;
    int lane = t & 31, wid = t >> 5;
    int warp_m = wid & 3, warp_n = wid >> 2;
    int rowBase = blockIdx.x * 128;
    int colBase = blockIdx.y * 64;

    float c[2][4][4];
    #pragma unroll
    for (int mt = 0; mt < 2; mt++)
        #pragma unroll
        for (int nt = 0; nt < 4; nt++)
            #pragma unroll
            for (int i = 0; i < 4; i++) c[mt][nt][i] = 0.f;

    for (int kc = 0; kc < K; kc += 64) {
        if (kc) __syncthreads();
        #pragma unroll
        for (int i = 0; i < 8; i++) {
            int idx = i * 256 + t;
            int r = idx >> 4, g = idx & 15;
            int row = rowBase + r;
            float4 f = (row < NN)
                ? *(const float4*)(X + (size_t)row * K + kc + g * 4)
                : make_float4(0.f, 0.f, 0.f, 0.f);
            *(__half2*)&As[r][g * 4]     = __floats2half2_rn(f.x, f.y);
            *(__half2*)&As[r][g * 4 + 2] = __floats2half2_rn(f.z, f.w);
        }
        #pragma unroll
        for (int i = 0; i < 4; i++) {
            int idx = i * 256 + t;
            int k = idx >> 4, g = idx & 15;
            float4 f = *(const float4*)(W + (size_t)(kc + k) * NO + colBase + g * 4);
            *(__half2*)&Bs[k][g * 4]     = __floats2half2_rn(f.x, f.y);
            *(__half2*)&Bs[k][g * 4 + 2] = __floats2half2_rn(f.z, f.w);
        }
        __syncthreads();
        #pragma unroll
        for (int ks = 0; ks < 4; ks++) {
            uint32_t a[2][4], b[2][4];
            #pragma unroll
            for (int mt = 0; mt < 2; mt++) {
                const __half* p = &As[warp_m * 32 + mt * 16 + (lane & 15)][ks * 16 + (lane >> 4) * 8];
                uint32_t addr = (uint32_t)__cvta_generic_to_shared(p);
                asm volatile("ldmatrix.sync.aligned.m8n8.x4.shared.b16 {%0,%1,%2,%3}, [%4];"
                    : "=r"(a[mt][0]), "=r"(a[mt][1]), "=r"(a[mt][2]), "=r"(a[mt][3])
                    : "r"(addr));
            }
            #pragma unroll
            for (int ng = 0; ng < 2; ng++) {
                const __half* p = &Bs[ks * 16 + (lane & 15)][warp_n * 32 + ng * 16 + (lane >> 4) * 8];
                uint32_t addr = (uint32_t)__cvta_generic_to_shared(p);
                asm volatile("ldmatrix.sync.aligned.m8n8.x4.trans.shared.b16 {%0,%1,%2,%3}, [%4];"
                    : "=r"(b[ng][0]), "=r"(b[ng][1]), "=r"(b[ng][2]), "=r"(b[ng][3])
                    : "r"(addr));
            }
            #pragma unroll
            for (int mt = 0; mt < 2; mt++)
                #pragma unroll
                for (int nt = 0; nt < 4; nt++) {
                    uint32_t b0 = b[nt >> 1][(nt & 1) * 2];
                    uint32_t b1 = b[nt >> 1][(nt & 1) * 2 + 1];
                    asm volatile(
                        "mma.sync.aligned.m16n8k16.row.col.f32.f16.f16.f32 "
                        "{%0,%1,%2,%3}, {%4,%5,%6,%7}, {%8,%9}, {%0,%1,%2,%3};"
                        : "+f"(c[mt][nt][0]), "+f"(c[mt][nt][1]),
                          "+f"(c[mt][nt][2]), "+f"(c[mt][nt][3])
                        : "r"(a[mt][0]), "r"(a[mt][1]), "r"(a[mt][2]), "r"(a[mt][3]),
                          "r"(b0), "r"(b1));
                }
        }
    }
    #pragma unroll
    for (int mt = 0; mt < 2; mt++) {
        int r0 = rowBase + warp_m * 32 + mt * 16 + (lane >> 2);
        #pragma unroll
        for (int nt = 0; nt < 4; nt++) {
            int col = colBase + warp_n * 32 + nt * 8 + (lane & 3) * 2;
            if (r0 < NN)
                *(__half2*)(Y + (size_t)r0 * NO + col) = __floats2half2_rn(c[mt][nt][0], c[mt][nt][1]);
            if (r0 + 8 < NN)
                *(__half2*)(Y + (size_t)(r0 + 8) * NO + col) = __floats2half2_rn(c[mt][nt][2], c[mt][nt][3]);
        }
    }
}

// ---------------- GAT attention coefficients from fp16 features -------------
template <int CH>
__global__ __launch_bounds__(256) void esed_kernel(const __half* __restrict__ hb,
                                                   const float* __restrict__ asrc,
                                                   const float* __restrict__ adst,
                                                   float* __restrict__ es,
                                                   float* __restrict__ ed) {
    int wid = (blockIdx.x * blockDim.x + threadIdx.x) >> 5;
    int l   = threadIdx.x & 31;
    if (wid >= NN * 8) return;
    int n = wid >> 3, hh = wid & 7;
    const __half* hp = hb + (size_t)n * (8 * CH) + hh * CH;
    const float* as = asrc + hh * CH;
    const float* ad = adst + hh * CH;
    float s, d;
    if (CH == 64) {
        float2 v = __half22float2(*(const __half2*)(hp + 2 * l));
        s = v.x * as[2 * l] + v.y * as[2 * l + 1];
        d = v.x * ad[2 * l] + v.y * ad[2 * l + 1];
    } else {
        float v = __half2float(hp[l]);
        s = v * as[l];
        d = v * ad[l];
    }
    s = warp_sum(s);
    d = warp_sum(d);
    if (l == 0) { es[n * 8 + hh] = s; ed[n * 8 + hh] = d; }
}

// ---------------- GCN aggregation (fp16 in) + bias + BN(eval) + ReLU --------
// R7 form: one warp per dst node; lane owns channel pair (2l, 2l+1).
__global__ __launch_bounds__(256) void gcn_agg_kernel(const __half* __restrict__ h,
                                                      const float* __restrict__ bias,
                                                      const float* __restrict__ gamma,
                                                      const float* __restrict__ beta,
                                                      const float* __restrict__ mean,
                                                      const float* __restrict__ var,
                                                      float* __restrict__ out) {
    int w = (blockIdx.x * blockDim.x + threadIdx.x) >> 5;
    int l = threadIdx.x & 31;
    if (w >= NN) return;
    int s0 = g_rowptr[w], s1 = g_rowptr[w + 1];
    float a0 = 0.f, a1 = 0.f;
    const __half2* hb = (const __half2*)h;
    for (int i = s0; i < s1; i++) {
        int s = g_colsrc[i];
        float dv = g_dinv[s];
        float2 v = __half22float2(hb[s * 32 + l]);
        a0 += dv * v.x;
        a1 += dv * v.y;
    }
    float dd = g_dinv[w];
    float2 bi = ((const float2*)bias)[l];
    float2 me = ((const float2*)mean)[l];
    float2 va = ((const float2*)var)[l];
    float2 ga = ((const float2*)gamma)[l];
    float2 be = ((const float2*)beta)[l];
    float v0 = a0 * dd + bi.x;
    float v1 = a1 * dd + bi.y;
    v0 = (v0 - me.x) * rsqrtf(va.x + BN_EPS) * ga.x + be.x;
    v1 = (v1 - me.y) * rsqrtf(va.y + BN_EPS) * ga.y + be.y;
    ((float2*)(out + (size_t)w * 64))[l] = make_float2(fmaxf(v0, 0.f), fmaxf(v1, 0.f));
}

// ---------------- GAT-64 aggregation: TWO warps per dst (4 heads each) ------
// Warp pair (2d, 2d+1) in same block; partials combined via shared memory.
// Lane owns channel pair (2l, 2l+1). Deterministic: serial edge walk per warp,
// fixed own+partner combine order.
__global__ __launch_bounds__(256) void gat_agg64_kernel(const __half* __restrict__ hb,
                                                        const float* __restrict__ es,
                                                        const float* __restrict__ ed,
                                                        const float* __restrict__ bias,
                                                        float* __restrict__ out) {
    __shared__ float2 sh[8][32];
    int wib = threadIdx.x >> 5;                 // warp in block (0..7)
    int gw  = blockIdx.x * 8 + wib;             // global warp
    int d   = gw >> 1;
    int hg  = gw & 1;                           // head group: heads hg*4..hg*4+3
    int l   = threadIdx.x & 31;
    if (d >= NN) return;                        // exact grid: never taken
    int s0 = g_rowptr[d], s1 = g_rowptr[d + 1];
    int base = hg * 4;

    float edv[4];
    {
        float4 e = *(const float4*)(ed + d * 8 + base);
        edv[0] = e.x; edv[1] = e.y; edv[2] = e.z; edv[3] = e.w;
    }

    // pass 1: per-head max (lane-strided; order-independent)
    float m[4] = {-1e30f, -1e30f, -1e30f, -1e30f};
    for (int i = s0 + l; i < s1; i += 32) {
        int s = g_colsrc[i];
        float4 e = *(const float4*)(es + s * 8 + base);
        float ev[4] = {e.x, e.y, e.z, e.w};
        #pragma unroll
        for (int h = 0; h < 4; h++) m[h] = fmaxf(m[h], lrelu(ev[h] + edv[h]));
    }
    #pragma unroll
    for (int h = 0; h < 4; h++) m[h] = warp_max(m[h]);

    // pass 2: fused unnormalized weights + weighted feature sums.
    float den = 0.f;
    float acc0[4] = {0.f, 0.f, 0.f, 0.f};
    float acc1[4] = {0.f, 0.f, 0.f, 0.f};
    const __half2* hp2 = (const __half2*)hb;
    for (int i = s0; i < s1; i++) {
        int s = g_colsrc[i];
        float wv = 0.f;
        if (l < 4) wv = __expf(lrelu(es[s * 8 + base + l] + edv[l]) - m[l]);
        den += wv;
        size_t fb = (size_t)s * 256 + base * 32 + l;
        #pragma unroll
        for (int h = 0; h < 4; h++) {
            float wh = __shfl_sync(0xffffffffu, wv, h);
            float2 f = __half22float2(hp2[fb + h * 32]);
            acc0[h] += wh * f.x;
            acc1[h] += wh * f.y;
        }
    }

    float pv0 = 0.f, pv1 = 0.f;
    #pragma unroll
    for (int h = 0; h < 4; h++) {
        float rd = 1.f / (__shfl_sync(0xffffffffu, den, h) + 1e-16f);
        pv0 += acc0[h] * rd;
        pv1 += acc1[h] * rd;
    }

    // combine the two head-group partials (own + partner, fixed order)
    sh[wib][l] = make_float2(pv0, pv1);
    __syncthreads();
    if (hg == 0) {
        float2 pr = sh[wib + 1][l];
        float2 bi = ((const float2*)bias)[l];
        float v0 = (pv0 + pr.x) * 0.125f + bi.x;
        float v1 = (pv1 + pr.y) * 0.125f + bi.y;
        ((float2*)(out + (size_t)d * 64))[l] =
            make_float2(fmaxf(v0, 0.f), fmaxf(v1, 0.f));   // ReLU (layer 2 only)
    }
}

// ---------------- GAT-32 aggregation (R7 form) + log_softmax ----------------
__global__ __launch_bounds__(256) void gat_agg32_kernel(const __half* __restrict__ hb,
                                                        const float* __restrict__ es,
                                                        const float* __restrict__ ed,
                                                        const float* __restrict__ bias,
                                                        float* __restrict__ out) {
    int d = (blockIdx.x * blockDim.x + threadIdx.x) >> 5;
    int l = threadIdx.x & 31;
    if (d >= NN) return;
    int s0 = g_rowptr[d], s1 = g_rowptr[d + 1];

    float edv[8];
    {
        const float4* e4 = (const float4*)(ed + d * 8);
        float4 a = e4[0], b = e4[1];
        edv[0] = a.x; edv[1] = a.y; edv[2] = a.z; edv[3] = a.w;
        edv[4] = b.x; edv[5] = b.y; edv[6] = b.z; edv[7] = b.w;
    }

    float m[8];
    #pragma unroll
    for (int h = 0; h < 8; h++) m[h] = -1e30f;
    for (int i = s0 + l; i < s1; i += 32) {
        int s = g_colsrc[i];
        const float4* e4 = (const float4*)(es + s * 8);
        float4 a = e4[0], b = e4[1];
        float ev[8] = {a.x, a.y, a.z, a.w, b.x, b.y, b.z, b.w};
        #pragma unroll
        for (int h = 0; h < 8; h++) m[h] = fmaxf(m[h], lrelu(ev[h] + edv[h]));
    }
    #pragma unroll
    for (int h = 0; h < 8; h++) m[h] = warp_max(m[h]);

    float den = 0.f;
    float acc0[8];
    #pragma unroll
    for (int h = 0; h < 8; h++) acc0[h] = 0.f;
    for (int i = s0; i < s1; i++) {
        int s = g_colsrc[i];
        float wv = 0.f;
        if (l < 8) wv = __expf(lrelu(es[s * 8 + l] + edv[l]) - m[l]);
        den += wv;
        const __half* hp = hb + (size_t)s * 256;
        #pragma unroll
        for (int h = 0; h < 8; h++) {
            float wh = __shfl_sync(0xffffffffu, wv, h);
            acc0[h] += wh * __half2float(hp[h * 32 + l]);
        }
    }

    float v0 = 0.f;
    #pragma unroll
    for (int h = 0; h < 8; h++) {
        float rd = 1.f / (__shfl_sync(0xffffffffu, den, h) + 1e-16f);
        v0 += acc0[h] * rd;
    }

    v0 = v0 * 0.125f + bias[l];
    float mx = warp_max(v0);
    float se = warp_sum(expf(v0 - mx));
    v0 = v0 - mx - logf(se);
    out[(size_t)d * 32 + l] = v0;
}

// ---------------- launch ----------------
extern "C" void kernel_launch(void* const* d_in, const int* in_sizes, int n_in,
                              void* d_out, int out_size) {
    const float* X        = (const float*)d_in[0];
    const void*  EI       = d_in[1];
    const float* gcn1_w   = (const float*)d_in[2];
    const float* gcn1_b   = (const float*)d_in[3];
    const float* bn1_g    = (const float*)d_in[4];
    const float* bn1_be   = (const float*)d_in[5];
    const float* bn1_m    = (const float*)d_in[6];
    const float* bn1_v    = (const float*)d_in[7];
    const float* gat1_w   = (const float*)d_in[8];
    const float* gat1_as  = (const float*)d_in[9];
    const float* gat1_ad  = (const float*)d_in[10];
    const float* gat1_b   = (const float*)d_in[11];
    const float* gcn2_w   = (const float*)d_in[12];
    const float* gcn2_b   = (const float*)d_in[13];
    const float* bn2_g    = (const float*)d_in[14];
    const float* bn2_be   = (const float*)d_in[15];
    const float* bn2_m    = (const float*)d_in[16];
    const float* bn2_v    = (const float*)d_in[17];
    const float* gat2_w   = (const float*)d_in[18];
    const float* gat2_as  = (const float*)d_in[19];
    const float* gat2_ad  = (const float*)d_in[20];
    const float* gat2_b   = (const float*)d_in[21];
    float* OUT = (float*)d_out;

    float *bufA, *bufB, *es, *ed;
    __half* hbuf;
    int* degPtr;
    cudaGetSymbolAddress((void**)&bufA,   g_bufA);
    cudaGetSymbolAddress((void**)&bufB,   g_bufB);
    cudaGetSymbolAddress((void**)&hbuf,   g_hbuf);
    cudaGetSymbolAddress((void**)&es,     g_es);
    cudaGetSymbolAddress((void**)&ed,     g_ed);
    cudaGetSymbolAddress((void**)&degPtr, g_deg);

    const int TB = 256;
    int gRows      = (NN + 127) / 128;   // 391
    int aggBlocks  = (NN * 32 + TB - 1) / TB;
    int agg2Blocks = (NN * 2 * 32) / TB;              // 12500, exact
    int esedBlocks = (NN * 8 * 32 + TB - 1) / TB;

    // graph build, with tc_gemm1 placed 5th so ncu (-s 5) captures it.
    detect_kernel<<<1, 32>>>((const int*)EI);                 // 1
    cudaMemsetAsync(degPtr, 0, NN * sizeof(int));             // 2
    convert_count_kernel<<<(EE + TB - 1) / TB, TB>>>(EI);     // 3
    bsum_kernel<<<NB, 256>>>();                               // 4
    tc_gemm_kernel<128, 64><<<dim3(gRows, 1), TB>>>(X, gcn1_w, hbuf);  // 5 <- profiled
    bscan_kernel<<<1, 256>>>();
    rowptr_kernel<<<NB, 256>>>();
    fill_kernel<<<(E2 + TB - 1) / TB, TB>>>();
    sort_kernel<<<(NN + TB - 1) / TB, TB>>>();

    // layer 1: GCN -> BN -> ReLU
    gcn_agg_kernel<<<aggBlocks, TB>>>(hbuf, gcn1_b, bn1_g, bn1_be, bn1_m, bn1_v, bufB);

    // layer 2: GAT(8 heads, 64 ch, mean) -> ReLU  [2 warps/node]
    tc_gemm_kernel<64, 512><<<dim3(gRows, 8), TB>>>(bufB, gat1_w, hbuf);
    esed_kernel<64><<<esedBlocks, TB>>>(hbuf, gat1_as, gat1_ad, es, ed);
    gat_agg64_kernel<<<agg2Blocks, TB>>>(hbuf, es, ed, gat1_b, bufA);

    // layer 3: GCN -> BN -> ReLU
    tc_gemm_kernel<64, 64><<<dim3(gRows, 1), TB>>>(bufA, gcn2_w, hbuf);
    gcn_agg_kernel<<<aggBlocks, TB>>>(hbuf, gcn2_b, bn2_g, bn2_be, bn2_m, bn2_v, bufB);

    // layer 4: GAT(8 heads, 32 ch, mean) + log_softmax
    tc_gemm_kernel<64, 256><<<dim3(gRows, 4), TB>>>(bufB, gat2_w, hbuf);
    esed_kernel<32><<<esedBlocks, TB>>>(hbuf, gat2_as, gat2_ad, es, ed);
    gat_agg32_kernel<<<aggBlocks, TB>>>(hbuf, es, ed, gat2_b, OUT);
}

// round 13
// speedup vs baseline: 1.5113x; 1.3253x over previous
#include <cuda_runtime.h>
#include <cuda_fp16.h>
#include <math.h>
#include <stdint.h>

#define NN 50000
#define EE 800000
#define E2 (EE + NN)
#define NB ((NN + 255) / 256)
#define BN_EPS 1e-5f

// ---------------- scratch (static __device__, no allocations) ----------------
__device__ int    g_is64;
__device__ int    g_src[EE];
__device__ int    g_dst[EE];
__device__ int    g_deg[NN];
__device__ int    g_bsum[256];
__device__ int    g_boff[256];
__device__ int    g_rowptr[NN + 1];
__device__ int    g_fill[NN];
__device__ int    g_colsrc[E2];
__device__ float  g_dinv[NN];
__device__ __half g_hA[NN * 64];
__device__ __half g_hB[NN * 64];
__device__ __half g_hbuf[(size_t)NN * 512];   // 51.2 MB fp16 feature buffer
__device__ float  g_es[NN * 8];
__device__ float  g_ed[NN * 8];

// ---------------- helpers ----------------
__device__ __forceinline__ float warp_max(float v) {
    #pragma unroll
    for (int o = 16; o; o >>= 1) v = fmaxf(v, __shfl_xor_sync(0xffffffffu, v, o));
    return v;
}
__device__ __forceinline__ float warp_sum(float v) {
    #pragma unroll
    for (int o = 16; o; o >>= 1) v += __shfl_xor_sync(0xffffffffu, v, o);
    return v;
}
__device__ __forceinline__ float lrelu(float x) { return x > 0.f ? x : 0.2f * x; }

// ---------------- graph-structure kernels ----------------
__global__ void detect_kernel(const int* __restrict__ ei) {
    int l = threadIdx.x;
    int any = 0;
    #pragma unroll
    for (int j = 0; j < 32; j++) any |= ei[2 * (j * 32 + l) + 1];
    #pragma unroll
    for (int o = 16; o; o >>= 1) any |= __shfl_xor_sync(0xffffffffu, any, o);
    if (l == 0) g_is64 = (any == 0) ? 1 : 0;
}

__global__ void convert_count_kernel(const void* __restrict__ ei) {
    int e = blockIdx.x * blockDim.x + threadIdx.x;
    if (e >= EE) return;
    int s, d;
    if (g_is64) {
        const long long* p = (const long long*)ei;
        s = (int)p[e];
        d = (int)p[EE + e];
    } else {
        const int* p = (const int*)ei;
        s = p[e];
        d = p[EE + e];
    }
    g_src[e] = s;
    g_dst[e] = d;
    atomicAdd(&g_deg[d], 1);
}

__global__ __launch_bounds__(256) void bsum_kernel() {
    __shared__ int sh[256];
    int t = threadIdx.x;
    int n = blockIdx.x * 256 + t;
    int v = (n < NN) ? (g_deg[n] + 1) : 0;
    sh[t] = v;
    __syncthreads();
    #pragma unroll
    for (int o = 128; o; o >>= 1) {
        if (t < o) sh[t] += sh[t + o];
        __syncthreads();
    }
    if (t == 0) g_bsum[blockIdx.x] = sh[0];
}

__global__ __launch_bounds__(256) void bscan_kernel() {
    __shared__ int sh[256];
    int t = threadIdx.x;
    int v = (t < NB) ? g_bsum[t] : 0;
    sh[t] = v;
    __syncthreads();
    #pragma unroll
    for (int o = 1; o < 256; o <<= 1) {
        int u = (t >= o) ? sh[t - o] : 0;
        __syncthreads();
        sh[t] += u;
        __syncthreads();
    }
    g_boff[t] = sh[t] - v;
}

__global__ __launch_bounds__(256) void rowptr_kernel() {
    __shared__ int sh[256];
    int t = threadIdx.x;
    int n = blockIdx.x * 256 + t;
    int v = (n < NN) ? (g_deg[n] + 1) : 0;
    sh[t] = v;
    __syncthreads();
    #pragma unroll
    for (int o = 1; o < 256; o <<= 1) {
        int u = (t >= o) ? sh[t - o] : 0;
        __syncthreads();
        sh[t] += u;
        __syncthreads();
    }
    int excl = sh[t] - v + g_boff[blockIdx.x];
    if (n < NN) {
        g_rowptr[n] = excl;
        g_fill[n]   = excl;
        g_dinv[n]   = rsqrtf((float)v);
    }
    if (n == NN - 1) g_rowptr[NN] = excl + v;
}

__global__ void fill_kernel() {
    int idx = blockIdx.x * blockDim.x + threadIdx.x;
    if (idx >= E2) return;
    int s, d;
    if (idx < EE) { s = g_src[idx]; d = g_dst[idx]; }
    else          { s = d = idx - EE; }
    int pos = atomicAdd(&g_fill[d], 1);
    g_colsrc[pos] = s;
}

__global__ void sort_kernel() {
    int r = blockIdx.x * blockDim.x + threadIdx.x;
    if (r >= NN) return;
    int s0 = g_rowptr[r], s1 = g_rowptr[r + 1];
    for (int i = s0 + 1; i < s1; i++) {
        int v = g_colsrc[i];
        int j = i - 1;
        while (j >= s0 && g_colsrc[j] > v) { g_colsrc[j + 1] = g_colsrc[j]; j--; }
        g_colsrc[j + 1] = v;
    }
}

// ---------------- tensor-core GEMM: Y(fp16)[M,NO] = X[M,K] @ W[K,NO] --------
// HALF_IN: A matrix is fp16 (raw copy into smem). DINV: scale output row r by
// g_dinv[r] before the fp16 store (folds GCN source normalization into GEMM).
template <int K, int NO, bool HALF_IN, bool DINV>
__global__ __launch_bounds__(256) void tc_gemm_kernel(const void* __restrict__ Xv,
                                                      const float* __restrict__ W,
                                                      __half* __restrict__ Y) {
    __shared__ __half As[128][72];
    __shared__ __half Bs[64][72];
    int t = threadIdx.x;
    int lane = t & 31, wid = t >> 5;
    int warp_m = wid & 3, warp_n = wid >> 2;
    int rowBase = blockIdx.x * 128;
    int colBase = blockIdx.y * 64;

    float c[2][4][4];
    #pragma unroll
    for (int mt = 0; mt < 2; mt++)
        #pragma unroll
        for (int nt = 0; nt < 4; nt++)
            #pragma unroll
            for (int i = 0; i < 4; i++) c[mt][nt][i] = 0.f;

    for (int kc = 0; kc < K; kc += 64) {
        if (kc) __syncthreads();
        // stage A
        if (HALF_IN) {
            const __half* Xh = (const __half*)Xv;
            #pragma unroll
            for (int i = 0; i < 4; i++) {
                int idx = i * 256 + t;
                int r = idx >> 3, g = idx & 7;          // 8 x 16B chunks per row
                int row = rowBase + r;
                uint4 u = (row < NN)
                    ? *(const uint4*)(Xh + (size_t)row * K + kc + g * 8)
                    : make_uint4(0u, 0u, 0u, 0u);
                *(uint4*)&As[r][g * 8] = u;
            }
        } else {
            const float* Xf = (const float*)Xv;
            #pragma unroll
            for (int i = 0; i < 8; i++) {
                int idx = i * 256 + t;
                int r = idx >> 4, g = idx & 15;
                int row = rowBase + r;
                float4 f = (row < NN)
                    ? *(const float4*)(Xf + (size_t)row * K + kc + g * 4)
                    : make_float4(0.f, 0.f, 0.f, 0.f);
                *(__half2*)&As[r][g * 4]     = __floats2half2_rn(f.x, f.y);
                *(__half2*)&As[r][g * 4 + 2] = __floats2half2_rn(f.z, f.w);
            }
        }
        // stage B
        #pragma unroll
        for (int i = 0; i < 4; i++) {
            int idx = i * 256 + t;
            int k = idx >> 4, g = idx & 15;
            float4 f = *(const float4*)(W + (size_t)(kc + k) * NO + colBase + g * 4);
            *(__half2*)&Bs[k][g * 4]     = __floats2half2_rn(f.x, f.y);
            *(__half2*)&Bs[k][g * 4 + 2] = __floats2half2_rn(f.z, f.w);
        }
        __syncthreads();
        #pragma unroll
        for (int ks = 0; ks < 4; ks++) {
            uint32_t a[2][4], b[2][4];
            #pragma unroll
            for (int mt = 0; mt < 2; mt++) {
                const __half* p = &As[warp_m * 32 + mt * 16 + (lane & 15)][ks * 16 + (lane >> 4) * 8];
                uint32_t addr = (uint32_t)__cvta_generic_to_shared(p);
                asm volatile("ldmatrix.sync.aligned.m8n8.x4.shared.b16 {%0,%1,%2,%3}, [%4];"
                    : "=r"(a[mt][0]), "=r"(a[mt][1]), "=r"(a[mt][2]), "=r"(a[mt][3])
                    : "r"(addr));
            }
            #pragma unroll
            for (int ng = 0; ng < 2; ng++) {
                const __half* p = &Bs[ks * 16 + (lane & 15)][warp_n * 32 + ng * 16 + (lane >> 4) * 8];
                uint32_t addr = (uint32_t)__cvta_generic_to_shared(p);
                asm volatile("ldmatrix.sync.aligned.m8n8.x4.trans.shared.b16 {%0,%1,%2,%3}, [%4];"
                    : "=r"(b[ng][0]), "=r"(b[ng][1]), "=r"(b[ng][2]), "=r"(b[ng][3])
                    : "r"(addr));
            }
            #pragma unroll
            for (int mt = 0; mt < 2; mt++)
                #pragma unroll
                for (int nt = 0; nt < 4; nt++) {
                    uint32_t b0 = b[nt >> 1][(nt & 1) * 2];
                    uint32_t b1 = b[nt >> 1][(nt & 1) * 2 + 1];
                    asm volatile(
                        "mma.sync.aligned.m16n8k16.row.col.f32.f16.f16.f32 "
                        "{%0,%1,%2,%3}, {%4,%5,%6,%7}, {%8,%9}, {%0,%1,%2,%3};"
                        : "+f"(c[mt][nt][0]), "+f"(c[mt][nt][1]),
                          "+f"(c[mt][nt][2]), "+f"(c[mt][nt][3])
                        : "r"(a[mt][0]), "r"(a[mt][1]), "r"(a[mt][2]), "r"(a[mt][3]),
                          "r"(b0), "r"(b1));
                }
        }
    }
    #pragma unroll
    for (int mt = 0; mt < 2; mt++) {
        int r0 = rowBase + warp_m * 32 + mt * 16 + (lane >> 2);
        float dv0 = 1.f, dv1 = 1.f;
        if (DINV) {
            dv0 = (r0 < NN) ? g_dinv[r0] : 0.f;
            dv1 = (r0 + 8 < NN) ? g_dinv[r0 + 8] : 0.f;
        }
        #pragma unroll
        for (int nt = 0; nt < 4; nt++) {
            int col = colBase + warp_n * 32 + nt * 8 + (lane & 3) * 2;
            if (r0 < NN)
                *(__half2*)(Y + (size_t)r0 * NO + col) =
                    __floats2half2_rn(c[mt][nt][0] * dv0, c[mt][nt][1] * dv0);
            if (r0 + 8 < NN)
                *(__half2*)(Y + (size_t)(r0 + 8) * NO + col) =
                    __floats2half2_rn(c[mt][nt][2] * dv1, c[mt][nt][3] * dv1);
        }
    }
}

// ---------------- GAT attention coefficients from fp16 features -------------
template <int CH>
__global__ __launch_bounds__(256) void esed_kernel(const __half* __restrict__ hb,
                                                   const float* __restrict__ asrc,
                                                   const float* __restrict__ adst,
                                                   float* __restrict__ es,
                                                   float* __restrict__ ed) {
    int wid = (blockIdx.x * blockDim.x + threadIdx.x) >> 5;
    int l   = threadIdx.x & 31;
    if (wid >= NN * 8) return;
    int n = wid >> 3, hh = wid & 7;
    const __half* hp = hb + (size_t)n * (8 * CH) + hh * CH;
    const float* as = asrc + hh * CH;
    const float* ad = adst + hh * CH;
    float s, d;
    if (CH == 64) {
        float2 v = __half22float2(*(const __half2*)(hp + 2 * l));
        s = v.x * as[2 * l] + v.y * as[2 * l + 1];
        d = v.x * ad[2 * l] + v.y * ad[2 * l + 1];
    } else {
        float v = __half2float(hp[l]);
        s = v * as[l];
        d = v * ad[l];
    }
    s = warp_sum(s);
    d = warp_sum(d);
    if (l == 0) { es[n * 8 + hh] = s; ed[n * 8 + hh] = d; }
}

// ---------------- GCN aggregation (prescaled fp16 in) + BN(eval) + ReLU -----
// Features already scaled by dinv[src] in the GEMM epilogue.
// One warp per dst node; lane owns channel pair (2l, 2l+1). fp16 out.
__global__ __launch_bounds__(256) void gcn_agg_kernel(const __half* __restrict__ h,
                                                      const float* __restrict__ bias,
                                                      const float* __restrict__ gamma,
                                                      const float* __restrict__ beta,
                                                      const float* __restrict__ mean,
                                                      const float* __restrict__ var,
                                                      __half* __restrict__ out) {
    int w = (blockIdx.x * blockDim.x + threadIdx.x) >> 5;
    int l = threadIdx.x & 31;
    if (w >= NN) return;
    int s0 = g_rowptr[w], s1 = g_rowptr[w + 1];
    float a0 = 0.f, a1 = 0.f;
    const __half2* hb = (const __half2*)h;
    for (int i = s0; i < s1; i++) {
        int s = g_colsrc[i];
        float2 v = __half22float2(hb[s * 32 + l]);
        a0 += v.x;
        a1 += v.y;
    }
    float dd = g_dinv[w];
    float2 bi = ((const float2*)bias)[l];
    float2 me = ((const float2*)mean)[l];
    float2 va = ((const float2*)var)[l];
    float2 ga = ((const float2*)gamma)[l];
    float2 be = ((const float2*)beta)[l];
    float v0 = a0 * dd + bi.x;
    float v1 = a1 * dd + bi.y;
    v0 = (v0 - me.x) * rsqrtf(va.x + BN_EPS) * ga.x + be.x;
    v1 = (v1 - me.y) * rsqrtf(va.y + BN_EPS) * ga.y + be.y;
    ((__half2*)(out + (size_t)w * 64))[l] =
        __floats2half2_rn(fmaxf(v0, 0.f), fmaxf(v1, 0.f));
}

// ---------------- GAT-64 aggregation: single pass, no max-shift -------------
// Softmax is shift-invariant; logits are O(10) so exp is safe unshifted.
// One warp per dst; lane owns channel pair (2l,2l+1). Deterministic serial walk.
__global__ __launch_bounds__(256) void gat_agg64_kernel(const __half* __restrict__ hb,
                                                        const float* __restrict__ es,
                                                        const float* __restrict__ ed,
                                                        const float* __restrict__ bias,
                                                        __half* __restrict__ out) {
    int d = (blockIdx.x * blockDim.x + threadIdx.x) >> 5;
    int l = threadIdx.x & 31;
    if (d >= NN) return;
    int s0 = g_rowptr[d], s1 = g_rowptr[d + 1];

    float edv = 0.f;
    if (l < 8) edv = ed[d * 8 + l];

    float den = 0.f;
    float acc0[8], acc1[8];
    #pragma unroll
    for (int h = 0; h < 8; h++) { acc0[h] = 0.f; acc1[h] = 0.f; }
    const __half2* hp2 = (const __half2*)hb;
    for (int i = s0; i < s1; i++) {
        int s = g_colsrc[i];
        float wv = 0.f;
        if (l < 8) wv = __expf(lrelu(es[s * 8 + l] + edv));
        den += wv;
        size_t fb = (size_t)s * 256 + l;
        #pragma unroll
        for (int h = 0; h < 8; h++) {
            float wh = __shfl_sync(0xffffffffu, wv, h);
            float2 f = __half22float2(hp2[fb + h * 32]);
            acc0[h] += wh * f.x;
            acc1[h] += wh * f.y;
        }
    }

    float v0 = 0.f, v1 = 0.f;
    #pragma unroll
    for (int h = 0; h < 8; h++) {
        float rd = 1.f / (__shfl_sync(0xffffffffu, den, h) + 1e-16f);
        v0 += acc0[h] * rd;
        v1 += acc1[h] * rd;
    }

    float2 bi = ((const float2*)bias)[l];
    v0 = v0 * 0.125f + bi.x;
    v1 = v1 * 0.125f + bi.y;
    ((__half2*)(out + (size_t)d * 64))[l] =
        __floats2half2_rn(fmaxf(v0, 0.f), fmaxf(v1, 0.f));   // ReLU (layer 2)
}

// ---------------- GAT-32 aggregation: single pass + exact log_softmax -------
__global__ __launch_bounds__(256) void gat_agg32_kernel(const __half* __restrict__ hb,
                                                        const float* __restrict__ es,
                                                        const float* __restrict__ ed,
                                                        const float* __restrict__ bias,
                                                        float* __restrict__ out) {
    int d = (blockIdx.x * blockDim.x + threadIdx.x) >> 5;
    int l = threadIdx.x & 31;
    if (d >= NN) return;
    int s0 = g_rowptr[d], s1 = g_rowptr[d + 1];

    float edv = 0.f;
    if (l < 8) edv = ed[d * 8 + l];

    float den = 0.f;
    float acc0[8];
    #pragma unroll
    for (int h = 0; h < 8; h++) acc0[h] = 0.f;
    for (int i = s0; i < s1; i++) {
        int s = g_colsrc[i];
        float wv = 0.f;
        if (l < 8) wv = __expf(lrelu(es[s * 8 + l] + edv));
        den += wv;
        const __half* hp = hb + (size_t)s * 256;
        #pragma unroll
        for (int h = 0; h < 8; h++) {
            float wh = __shfl_sync(0xffffffffu, wv, h);
            acc0[h] += wh * __half2float(hp[h * 32 + l]);
        }
    }

    float v0 = 0.f;
    #pragma unroll
    for (int h = 0; h < 8; h++) {
        float rd = 1.f / (__shfl_sync(0xffffffffu, den, h) + 1e-16f);
        v0 += acc0[h] * rd;
    }

    v0 = v0 * 0.125f + bias[l];
    float mx = warp_max(v0);
    float se = warp_sum(expf(v0 - mx));
    v0 = v0 - mx - logf(se);
    out[(size_t)d * 32 + l] = v0;
}

// ---------------- launch ----------------
extern "C" void kernel_launch(void* const* d_in, const int* in_sizes, int n_in,
                              void* d_out, int out_size) {
    const float* X        = (const float*)d_in[0];
    const void*  EI       = d_in[1];
    const float* gcn1_w   = (const float*)d_in[2];
    const float* gcn1_b   = (const float*)d_in[3];
    const float* bn1_g    = (const float*)d_in[4];
    const float* bn1_be   = (const float*)d_in[5];
    const float* bn1_m    = (const float*)d_in[6];
    const float* bn1_v    = (const float*)d_in[7];
    const float* gat1_w   = (const float*)d_in[8];
    const float* gat1_as  = (const float*)d_in[9];
    const float* gat1_ad  = (const float*)d_in[10];
    const float* gat1_b   = (const float*)d_in[11];
    const float* gcn2_w   = (const float*)d_in[12];
    const float* gcn2_b   = (const float*)d_in[13];
    const float* bn2_g    = (const float*)d_in[14];
    const float* bn2_be   = (const float*)d_in[15];
    const float* bn2_m    = (const float*)d_in[16];
    const float* bn2_v    = (const float*)d_in[17];
    const float* gat2_w   = (const float*)d_in[18];
    const float* gat2_as  = (const float*)d_in[19];
    const float* gat2_ad  = (const float*)d_in[20];
    const float* gat2_b   = (const float*)d_in[21];
    float* OUT = (float*)d_out;

    float *es, *ed;
    __half *hA, *hB, *hbuf;
    int* degPtr;
    cudaGetSymbolAddress((void**)&hA,     g_hA);
    cudaGetSymbolAddress((void**)&hB,     g_hB);
    cudaGetSymbolAddress((void**)&hbuf,   g_hbuf);
    cudaGetSymbolAddress((void**)&es,     g_es);
    cudaGetSymbolAddress((void**)&ed,     g_ed);
    cudaGetSymbolAddress((void**)&degPtr, g_deg);

    const int TB = 256;
    int gRows      = (NN + 127) / 128;   // 391
    int aggBlocks  = (NN * 32 + TB - 1) / TB;
    int esedBlocks = (NN * 8 * 32 + TB - 1) / TB;

    // graph build
    detect_kernel<<<1, 32>>>((const int*)EI);
    cudaMemsetAsync(degPtr, 0, NN * sizeof(int));
    convert_count_kernel<<<(EE + TB - 1) / TB, TB>>>(EI);
    bsum_kernel<<<NB, 256>>>();
    bscan_kernel<<<1, 256>>>();
    rowptr_kernel<<<NB, 256>>>();        // produces dinv (needed by DINV gemms)
    fill_kernel<<<(E2 + TB - 1) / TB, TB>>>();
    sort_kernel<<<(NN + TB - 1) / TB, TB>>>();

    // layer 1: GCN -> BN -> ReLU  (gemm scales rows by dinv[src])
    tc_gemm_kernel<128, 64, false, true><<<dim3(gRows, 1), TB>>>(X, gcn1_w, hA);
    gcn_agg_kernel<<<aggBlocks, TB>>>(hA, gcn1_b, bn1_g, bn1_be, bn1_m, bn1_v, hB);

    // layer 2: GAT(8 heads, 64 ch, mean) -> ReLU
    tc_gemm_kernel<64, 512, true, false><<<dim3(gRows, 8), TB>>>(hB, gat1_w, hbuf);
    esed_kernel<64><<<esedBlocks, TB>>>(hbuf, gat1_as, gat1_ad, es, ed);
    gat_agg64_kernel<<<aggBlocks, TB>>>(hbuf, es, ed, gat1_b, hA);

    // layer 3: GCN -> BN -> ReLU
    tc_gemm_kernel<64, 64, true, true><<<dim3(gRows, 1), TB>>>(hA, gcn2_w, hbuf);
    gcn_agg_kernel<<<aggBlocks, TB>>>(hbuf, gcn2_b, bn2_g, bn2_be, bn2_m, bn2_v, hB);

    // layer 4: GAT(8 heads, 32 ch, mean) + log_softmax
    tc_gemm_kernel<64, 256, true, false><<<dim3(gRows, 4), TB>>>(hB, gat2_w, hbuf);
    esed_kernel<32><<<esedBlocks, TB>>>(hbuf, gat2_as, gat2_ad, es, ed);
    gat_agg32_kernel<<<aggBlocks, TB>>>(hbuf, es, ed, gat2_b, OUT);
}

// round 15
// speedup vs baseline: 1.8406x; 1.2179x over previous
#include <cuda_runtime.h>
#include <cuda_fp16.h>
#include <math.h>
#include <stdint.h>

#define NN 50000
#define EE 800000
#define E2 (EE + NN)
#define NB ((NN + 255) / 256)
#define BN_EPS 1e-5f

// ---------------- scratch (static __device__, no allocations) ----------------
__device__ int    g_is64;
__device__ int    g_src[EE];
__device__ int    g_dst[EE];
__device__ int    g_deg[NN];
__device__ int    g_bsum[256];
__device__ int    g_rowptr[NN + 1];
__device__ int    g_fill[NN];
__device__ int    g_colsrc[E2];
__device__ float  g_dinv[NN];
__device__ __half g_hA[NN * 64];
__device__ __half g_hB[NN * 64];
__device__ __half g_hbuf[(size_t)NN * 512];   // 51.2 MB fp16 feature buffer
__device__ float  g_es[NN * 8];
__device__ float  g_ed[NN * 8];
__device__ float  g_wcomb[64 * 16];           // [k][o]: o<8 -> W·asrc, o>=8 -> W·adst

// ---------------- helpers ----------------
__device__ __forceinline__ float warp_max(float v) {
    #pragma unroll
    for (int o = 16; o; o >>= 1) v = fmaxf(v, __shfl_xor_sync(0xffffffffu, v, o));
    return v;
}
__device__ __forceinline__ float warp_sum(float v) {
    #pragma unroll
    for (int o = 16; o; o >>= 1) v += __shfl_xor_sync(0xffffffffu, v, o);
    return v;
}
__device__ __forceinline__ float lrelu(float x) { return x > 0.f ? x : 0.2f * x; }

// ---------------- graph-structure kernels ----------------
__global__ void detect_kernel(const int* __restrict__ ei) {
    int l = threadIdx.x;
    int any = 0;
    #pragma unroll
    for (int j = 0; j < 32; j++) any |= ei[2 * (j * 32 + l) + 1];
    #pragma unroll
    for (int o = 16; o; o >>= 1) any |= __shfl_xor_sync(0xffffffffu, any, o);
    if (l == 0) g_is64 = (any == 0) ? 1 : 0;
}

__global__ void convert_count_kernel(const void* __restrict__ ei) {
    int e = blockIdx.x * blockDim.x + threadIdx.x;
    if (e >= EE) return;
    int s, d;
    if (g_is64) {
        const long long* p = (const long long*)ei;
        s = (int)p[e];
        d = (int)p[EE + e];
    } else {
        const int* p = (const int*)ei;
        s = p[e];
        d = p[EE + e];
    }
    g_src[e] = s;
    g_dst[e] = d;
    atomicAdd(&g_deg[d], 1);
}

__global__ __launch_bounds__(256) void bsum_kernel() {
    __shared__ int sh[256];
    int t = threadIdx.x;
    int n = blockIdx.x * 256 + t;
    int v = (n < NN) ? (g_deg[n] + 1) : 0;
    sh[t] = v;
    __syncthreads();
    #pragma unroll
    for (int o = 128; o; o >>= 1) {
        if (t < o) sh[t] += sh[t + o];
        __syncthreads();
    }
    if (t == 0) g_bsum[blockIdx.x] = sh[0];
}

// rowptr with block-sum scan folded in (each block scans the 196 sums itself).
__global__ __launch_bounds__(256) void rowptr_kernel() {
    __shared__ int sb[256];
    __shared__ int sh[256];
    int t = threadIdx.x;
    // scan block sums
    int bv = (t < NB) ? g_bsum[t] : 0;
    sb[t] = bv;
    __syncthreads();
    #pragma unroll
    for (int o = 1; o < 256; o <<= 1) {
        int u = (t >= o) ? sb[t - o] : 0;
        __syncthreads();
        sb[t] += u;
        __syncthreads();
    }
    int boff = (blockIdx.x == 0) ? 0 : sb[blockIdx.x - 1];
    // per-block scan of deg+1
    int n = blockIdx.x * 256 + t;
    int v = (n < NN) ? (g_deg[n] + 1) : 0;
    sh[t] = v;
    __syncthreads();
    #pragma unroll
    for (int o = 1; o < 256; o <<= 1) {
        int u = (t >= o) ? sh[t - o] : 0;
        __syncthreads();
        sh[t] += u;
        __syncthreads();
    }
    int excl = sh[t] - v + boff;
    if (n < NN) {
        g_rowptr[n] = excl;
        g_fill[n]   = excl;
        g_dinv[n]   = rsqrtf((float)v);
    }
    if (n == NN - 1) g_rowptr[NN] = excl + v;
}

__global__ void fill_kernel() {
    int idx = blockIdx.x * blockDim.x + threadIdx.x;
    if (idx >= E2) return;
    int s, d;
    if (idx < EE) { s = g_src[idx]; d = g_dst[idx]; }
    else          { s = d = idx - EE; }
    int pos = atomicAdd(&g_fill[d], 1);
    g_colsrc[pos] = s;
}

__global__ void sort_kernel() {
    int r = blockIdx.x * blockDim.x + threadIdx.x;
    if (r >= NN) return;
    int s0 = g_rowptr[r], s1 = g_rowptr[r + 1];
    for (int i = s0 + 1; i < s1; i++) {
        int v = g_colsrc[i];
        int j = i - 1;
        while (j >= s0 && g_colsrc[j] > v) { g_colsrc[j + 1] = g_colsrc[j]; j--; }
        g_colsrc[j + 1] = v;
    }
}

// ---------------- tensor-core GEMM: Y(fp16)[M,NO] = X[M,K] @ W[K,NO] --------
template <int K, int NO, bool HALF_IN, bool DINV>
__global__ __launch_bounds__(256) void tc_gemm_kernel(const void* __restrict__ Xv,
                                                      const float* __restrict__ W,
                                                      __half* __restrict__ Y) {
    __shared__ __half As[128][72];
    __shared__ __half Bs[64][72];
    int t = threadIdx.x;
    int lane = t & 31, wid = t >> 5;
    int warp_m = wid & 3, warp_n = wid >> 2;
    int rowBase = blockIdx.x * 128;
    int colBase = blockIdx.y * 64;

    float c[2][4][4];
    #pragma unroll
    for (int mt = 0; mt < 2; mt++)
        #pragma unroll
        for (int nt = 0; nt < 4; nt++)
            #pragma unroll
            for (int i = 0; i < 4; i++) c[mt][nt][i] = 0.f;

    for (int kc = 0; kc < K; kc += 64) {
        if (kc) __syncthreads();
        if (HALF_IN) {
            const __half* Xh = (const __half*)Xv;
            #pragma unroll
            for (int i = 0; i < 4; i++) {
                int idx = i * 256 + t;
                int r = idx >> 3, g = idx & 7;
                int row = rowBase + r;
                uint4 u = (row < NN)
                    ? *(const uint4*)(Xh + (size_t)row * K + kc + g * 8)
                    : make_uint4(0u, 0u, 0u, 0u);
                *(uint4*)&As[r][g * 8] = u;
            }
        } else {
            const float* Xf = (const float*)Xv;
            #pragma unroll
            for (int i = 0; i < 8; i++) {
                int idx = i * 256 + t;
                int r = idx >> 4, g = idx & 15;
                int row = rowBase + r;
                float4 f = (row < NN)
                    ? *(const float4*)(Xf + (size_t)row * K + kc + g * 4)
                    : make_float4(0.f, 0.f, 0.f, 0.f);
                *(__half2*)&As[r][g * 4]     = __floats2half2_rn(f.x, f.y);
                *(__half2*)&As[r][g * 4 + 2] = __floats2half2_rn(f.z, f.w);
            }
        }
        #pragma unroll
        for (int i = 0; i < 4; i++) {
            int idx = i * 256 + t;
            int k = idx >> 4, g = idx & 15;
            float4 f = *(const float4*)(W + (size_t)(kc + k) * NO + colBase + g * 4);
            *(__half2*)&Bs[k][g * 4]     = __floats2half2_rn(f.x, f.y);
            *(__half2*)&Bs[k][g * 4 + 2] = __floats2half2_rn(f.z, f.w);
        }
        __syncthreads();
        #pragma unroll
        for (int ks = 0; ks < 4; ks++) {
            uint32_t a[2][4], b[2][4];
            #pragma unroll
            for (int mt = 0; mt < 2; mt++) {
                const __half* p = &As[warp_m * 32 + mt * 16 + (lane & 15)][ks * 16 + (lane >> 4) * 8];
                uint32_t addr = (uint32_t)__cvta_generic_to_shared(p);
                asm volatile("ldmatrix.sync.aligned.m8n8.x4.shared.b16 {%0,%1,%2,%3}, [%4];"
                    : "=r"(a[mt][0]), "=r"(a[mt][1]), "=r"(a[mt][2]), "=r"(a[mt][3])
                    : "r"(addr));
            }
            #pragma unroll
            for (int ng = 0; ng < 2; ng++) {
                const __half* p = &Bs[ks * 16 + (lane & 15)][warp_n * 32 + ng * 16 + (lane >> 4) * 8];
                uint32_t addr = (uint32_t)__cvta_generic_to_shared(p);
                asm volatile("ldmatrix.sync.aligned.m8n8.x4.trans.shared.b16 {%0,%1,%2,%3}, [%4];"
                    : "=r"(b[ng][0]), "=r"(b[ng][1]), "=r"(b[ng][2]), "=r"(b[ng][3])
                    : "r"(addr));
            }
            #pragma unroll
            for (int mt = 0; mt < 2; mt++)
                #pragma unroll
                for (int nt = 0; nt < 4; nt++) {
                    uint32_t b0 = b[nt >> 1][(nt & 1) * 2];
                    uint32_t b1 = b[nt >> 1][(nt & 1) * 2 + 1];
                    asm volatile(
                        "mma.sync.aligned.m16n8k16.row.col.f32.f16.f16.f32 "
                        "{%0,%1,%2,%3}, {%4,%5,%6,%7}, {%8,%9}, {%0,%1,%2,%3};"
                        : "+f"(c[mt][nt][0]), "+f"(c[mt][nt][1]),
                          "+f"(c[mt][nt][2]), "+f"(c[mt][nt][3])
                        : "r"(a[mt][0]), "r"(a[mt][1]), "r"(a[mt][2]), "r"(a[mt][3]),
                          "r"(b0), "r"(b1));
                }
        }
    }
    #pragma unroll
    for (int mt = 0; mt < 2; mt++) {
        int r0 = rowBase + warp_m * 32 + mt * 16 + (lane >> 2);
        float dv0 = 1.f, dv1 = 1.f;
        if (DINV) {
            dv0 = (r0 < NN) ? g_dinv[r0] : 0.f;
            dv1 = (r0 + 8 < NN) ? g_dinv[r0 + 8] : 0.f;
        }
        #pragma unroll
        for (int nt = 0; nt < 4; nt++) {
            int col = colBase + warp_n * 32 + nt * 8 + (lane & 3) * 2;
            if (r0 < NN)
                *(__half2*)(Y + (size_t)r0 * NO + col) =
                    __floats2half2_rn(c[mt][nt][0] * dv0, c[mt][nt][1] * dv0);
            if (r0 + 8 < NN)
                *(__half2*)(Y + (size_t)(r0 + 8) * NO + col) =
                    __floats2half2_rn(c[mt][nt][2] * dv1, c[mt][nt][3] * dv1);
        }
    }
}

// ---------------- Wcomb precompute: wcomb[k][o] = sum_c W[k, h*CH+c] * a[h][c]
template <int CH, int NO>
__global__ void wprep_kernel(const float* __restrict__ W,
                             const float* __restrict__ asrc,
                             const float* __restrict__ adst) {
    int t = blockIdx.x * blockDim.x + threadIdx.x;
    if (t >= 1024) return;
    int k = t >> 4, o = t & 15;
    int h = o & 7;
    const float* a = (o < 8) ? asrc : adst;
    float s = 0.f;
    for (int c = 0; c < CH; c++)
        s += W[(size_t)k * NO + h * CH + c] * a[h * CH + c];
    g_wcomb[k * 16 + o] = s;
}

// ---------------- es/ed from x (fp16) @ wcomb: warp handles 2 nodes ---------
__global__ __launch_bounds__(256) void esed2_kernel(const __half* __restrict__ x,
                                                    float* __restrict__ es,
                                                    float* __restrict__ ed) {
    __shared__ float sw[1024];
    int t = threadIdx.x;
    for (int i = t; i < 1024; i += 256) sw[i] = g_wcomb[i];
    __syncthreads();
    int warp = (blockIdx.x * 256 + t) >> 5;
    int l = t & 31;
    int n = warp * 2 + (l >> 4);
    int o = l & 15;
    if (n >= NN) return;
    const __half2* xr = (const __half2*)(x + (size_t)n * 64);
    float acc = 0.f;
    #pragma unroll 8
    for (int g = 0; g < 32; g++) {
        float2 f = __half22float2(xr[g]);
        acc += f.x * sw[(2 * g) * 16 + o] + f.y * sw[(2 * g + 1) * 16 + o];
    }
    if (o < 8) es[n * 8 + o] = acc;
    else       ed[n * 8 + (o - 8)] = acc;
}

// ---------------- GCN aggregation (prescaled fp16 in) + BN(eval) + ReLU -----
__global__ __launch_bounds__(256) void gcn_agg_kernel(const __half* __restrict__ h,
                                                      const float* __restrict__ bias,
                                                      const float* __restrict__ gamma,
                                                      const float* __restrict__ beta,
                                                      const float* __restrict__ mean,
                                                      const float* __restrict__ var,
                                                      __half* __restrict__ out) {
    int w = (blockIdx.x * blockDim.x + threadIdx.x) >> 5;
    int l = threadIdx.x & 31;
    if (w >= NN) return;
    int s0 = g_rowptr[w], s1 = g_rowptr[w + 1];
    float a0 = 0.f, a1 = 0.f;
    const __half2* hb = (const __half2*)h;
    for (int i = s0; i < s1; i++) {
        int s = g_colsrc[i];
        float2 v = __half22float2(hb[s * 32 + l]);
        a0 += v.x;
        a1 += v.y;
    }
    float dd = g_dinv[w];
    float2 bi = ((const float2*)bias)[l];
    float2 me = ((const float2*)mean)[l];
    float2 va = ((const float2*)var)[l];
    float2 ga = ((const float2*)gamma)[l];
    float2 be = ((const float2*)beta)[l];
    float v0 = a0 * dd + bi.x;
    float v1 = a1 * dd + bi.y;
    v0 = (v0 - me.x) * rsqrtf(va.x + BN_EPS) * ga.x + be.x;
    v1 = (v1 - me.y) * rsqrtf(va.y + BN_EPS) * ga.y + be.y;
    ((__half2*)(out + (size_t)w * 64))[l] =
        __floats2half2_rn(fmaxf(v0, 0.f), fmaxf(v1, 0.f));
}

// ---------------- GAT-64 aggregation: vectorized (2x LDG.128/edge) ----------
// Load j (0..1), lane l covers head 4j+(l>>3), channels (l&7)*8 .. +7.
// Per-head accumulators; per-head normalize BEFORE cross-head xor-reduce.
__global__ __launch_bounds__(256) void gat_agg64_kernel(const __half* __restrict__ hb,
                                                        const float* __restrict__ es,
                                                        const float* __restrict__ ed,
                                                        const float* __restrict__ bias,
                                                        __half* __restrict__ out) {
    int d = (blockIdx.x * blockDim.x + threadIdx.x) >> 5;
    int l = threadIdx.x & 31;
    if (d >= NN) return;
    int s0 = g_rowptr[d], s1 = g_rowptr[d + 1];

    float edv = (l < 8) ? ed[d * 8 + l] : 0.f;
    int h0 = l >> 3;                 // head offsets: j*4 + h0

    float den = 0.f;
    float acc[2][8];
    #pragma unroll
    for (int j = 0; j < 2; j++)
        #pragma unroll
        for (int k = 0; k < 8; k++) acc[j][k] = 0.f;

    for (int i = s0; i < s1; i++) {
        int s = g_colsrc[i];
        float wv = 0.f;
        if (l < 8) wv = __expf(lrelu(es[s * 8 + l] + edv));
        den += wv;
        const uint4* hp = (const uint4*)(hb + (size_t)s * 512);
        #pragma unroll
        for (int j = 0; j < 2; j++) {
            float wh = __shfl_sync(0xffffffffu, wv, j * 4 + h0);
            uint4 u = hp[j * 32 + l];
            __half2* hx = (__half2*)&u;
            #pragma unroll
            for (int p = 0; p < 4; p++) {
                float2 f = __half22float2(hx[p]);
                acc[j][2 * p]     += wh * f.x;
                acc[j][2 * p + 1] += wh * f.y;
            }
        }
    }

    float v[8];
    #pragma unroll
    for (int k = 0; k < 8; k++) v[k] = 0.f;
    #pragma unroll
    for (int j = 0; j < 2; j++) {
        float dh = __shfl_sync(0xffffffffu, den, j * 4 + h0);
        float rd = 1.f / (dh + 1e-16f);
        #pragma unroll
        for (int k = 0; k < 8; k++) v[k] += acc[j][k] * rd;
    }
    // cross-head sum: lanes {l&7, +8, +16, +24} cover disjoint head sets
    #pragma unroll
    for (int k = 0; k < 8; k++) {
        v[k] += __shfl_xor_sync(0xffffffffu, v[k], 8);
        v[k] += __shfl_xor_sync(0xffffffffu, v[k], 16);
    }
    if (l < 8) {
        const float4* bi4 = (const float4*)(bias + l * 8);
        float4 b0 = bi4[0], b1 = bi4[1];
        float bb[8] = {b0.x, b0.y, b0.z, b0.w, b1.x, b1.y, b1.z, b1.w};
        __half2 o2[4];
        #pragma unroll
        for (int p = 0; p < 4; p++) {
            float x0 = fmaxf(v[2 * p]     * 0.125f + bb[2 * p], 0.f);
            float x1 = fmaxf(v[2 * p + 1] * 0.125f + bb[2 * p + 1], 0.f);
            o2[p] = __floats2half2_rn(x0, x1);
        }
        *(uint4*)(out + (size_t)d * 64 + l * 8) = *(uint4*)o2;
    }
}

// ---------------- GAT-32 aggregation: vectorized (2x LDG.64/edge) + logsm ---
// Load j (0..1), lane l covers head 4j+(l>>3), channels (l&7)*4 .. +3.
__global__ __launch_bounds__(256) void gat_agg32_kernel(const __half* __restrict__ hb,
                                                        const float* __restrict__ es,
                                                        const float* __restrict__ ed,
                                                        const float* __restrict__ bias,
                                                        float* __restrict__ out) {
    int d = (blockIdx.x * blockDim.x + threadIdx.x) >> 5;
    int l = threadIdx.x & 31;
    if (d >= NN) return;
    int s0 = g_rowptr[d], s1 = g_rowptr[d + 1];

    float edv = (l < 8) ? ed[d * 8 + l] : 0.f;
    int h0 = l >> 3;

    float den = 0.f;
    float acc[2][4];
    #pragma unroll
    for (int j = 0; j < 2; j++)
        #pragma unroll
        for (int k = 0; k < 4; k++) acc[j][k] = 0.f;

    for (int i = s0; i < s1; i++) {
        int s = g_colsrc[i];
        float wv = 0.f;
        if (l < 8) wv = __expf(lrelu(es[s * 8 + l] + edv));
        den += wv;
        const uint2* hp = (const uint2*)(hb + (size_t)s * 256);
        #pragma unroll
        for (int j = 0; j < 2; j++) {
            float wh = __shfl_sync(0xffffffffu, wv, j * 4 + h0);
            uint2 u = hp[j * 32 + l];
            __half2* hx = (__half2*)&u;
            #pragma unroll
            for (int p = 0; p < 2; p++) {
                float2 f = __half22float2(hx[p]);
                acc[j][2 * p]     += wh * f.x;
                acc[j][2 * p + 1] += wh * f.y;
            }
        }
    }

    float v[4];
    #pragma unroll
    for (int k = 0; k < 4; k++) v[k] = 0.f;
    #pragma unroll
    for (int j = 0; j < 2; j++) {
        float dh = __shfl_sync(0xffffffffu, den, j * 4 + h0);
        float rd = 1.f / (dh + 1e-16f);
        #pragma unroll
        for (int k = 0; k < 4; k++) v[k] += acc[j][k] * rd;
    }
    #pragma unroll
    for (int k = 0; k < 4; k++) {
        v[k] += __shfl_xor_sync(0xffffffffu, v[k], 8);
        v[k] += __shfl_xor_sync(0xffffffffu, v[k], 16);
    }
    // bias + mean-over-heads; channels (l&7)*4 .. +3 (duplicated 4x across warp)
    {
        float4 bb = *(const float4*)(bias + (l & 7) * 4);
        v[0] = v[0] * 0.125f + bb.x;
        v[1] = v[1] * 0.125f + bb.y;
        v[2] = v[2] * 0.125f + bb.z;
        v[3] = v[3] * 0.125f + bb.w;
    }
    // exact log_softmax over 32 channels (each channel appears 4x in warp)
    float mx = fmaxf(fmaxf(v[0], v[1]), fmaxf(v[2], v[3]));
    mx = warp_max(mx);
    float se = expf(v[0] - mx) + expf(v[1] - mx) + expf(v[2] - mx) + expf(v[3] - mx);
    se = 0.25f * warp_sum(se);
    float ls = mx + logf(se);
    if (l < 8) {
        float4 o;
        o.x = v[0] - ls; o.y = v[1] - ls; o.z = v[2] - ls; o.w = v[3] - ls;
        *(float4*)(out + (size_t)d * 32 + l * 4) = o;
    }
}

// ---------------- launch ----------------
extern "C" void kernel_launch(void* const* d_in, const int* in_sizes, int n_in,
                              void* d_out, int out_size) {
    const float* X        = (const float*)d_in[0];
    const void*  EI       = d_in[1];
    const float* gcn1_w   = (const float*)d_in[2];
    const float* gcn1_b   = (const float*)d_in[3];
    const float* bn1_g    = (const float*)d_in[4];
    const float* bn1_be   = (const float*)d_in[5];
    const float* bn1_m    = (const float*)d_in[6];
    const float* bn1_v    = (const float*)d_in[7];
    const float* gat1_w   = (const float*)d_in[8];
    const float* gat1_as  = (const float*)d_in[9];
    const float* gat1_ad  = (const float*)d_in[10];
    const float* gat1_b   = (const float*)d_in[11];
    const float* gcn2_w   = (const float*)d_in[12];
    const float* gcn2_b   = (const float*)d_in[13];
    const float* bn2_g    = (const float*)d_in[14];
    const float* bn2_be   = (const float*)d_in[15];
    const float* bn2_m    = (const float*)d_in[16];
    const float* bn2_v    = (const float*)d_in[17];
    const float* gat2_w   = (const float*)d_in[18];
    const float* gat2_as  = (const float*)d_in[19];
    const float* gat2_ad  = (const float*)d_in[20];
    const float* gat2_b   = (const float*)d_in[21];
    float* OUT = (float*)d_out;

    float *es, *ed;
    __half *hA, *hB, *hbuf;
    int* degPtr;
    cudaGetSymbolAddress((void**)&hA,     g_hA);
    cudaGetSymbolAddress((void**)&hB,     g_hB);
    cudaGetSymbolAddress((void**)&hbuf,   g_hbuf);
    cudaGetSymbolAddress((void**)&es,     g_es);
    cudaGetSymbolAddress((void**)&ed,     g_ed);
    cudaGetSymbolAddress((void**)&degPtr, g_deg);

    const int TB = 256;
    int gRows      = (NN + 127) / 128;   // 391
    int aggBlocks  = (NN * 32 + TB - 1) / TB;
    int esedBlocks = ((NN + 1) / 2 * 32 + TB - 1) / TB;

    // graph build
    detect_kernel<<<1, 32>>>((const int*)EI);
    cudaMemsetAsync(degPtr, 0, NN * sizeof(int));
    convert_count_kernel<<<(EE + TB - 1) / TB, TB>>>(EI);
    bsum_kernel<<<NB, 256>>>();
    rowptr_kernel<<<NB, 256>>>();
    fill_kernel<<<(E2 + TB - 1) / TB, TB>>>();
    sort_kernel<<<(NN + TB - 1) / TB, TB>>>();

    // layer 1: GCN -> BN -> ReLU
    tc_gemm_kernel<128, 64, false, true><<<dim3(gRows, 1), TB>>>(X, gcn1_w, hA);
    gcn_agg_kernel<<<aggBlocks, TB>>>(hA, gcn1_b, bn1_g, bn1_be, bn1_m, bn1_v, hB);

    // layer 2: GAT(8 heads, 64 ch, mean) -> ReLU
    wprep_kernel<64, 512><<<4, 256>>>(gat1_w, gat1_as, gat1_ad);
    tc_gemm_kernel<64, 512, true, false><<<dim3(gRows, 8), TB>>>(hB, gat1_w, hbuf);
    esed2_kernel<<<esedBlocks, TB>>>(hB, es, ed);
    gat_agg64_kernel<<<aggBlocks, TB>>>(hbuf, es, ed, gat1_b, hA);

    // layer 3: GCN -> BN -> ReLU
    tc_gemm_kernel<64, 64, true, true><<<dim3(gRows, 1), TB>>>(hA, gcn2_w, hbuf);
    gcn_agg_kernel<<<aggBlocks, TB>>>(hbuf, gcn2_b, bn2_g, bn2_be, bn2_m, bn2_v, hB);

    // layer 4: GAT(8 heads, 32 ch, mean) + log_softmax
    wprep_kernel<32, 256><<<4, 256>>>(gat2_w, gat2_as, gat2_ad);
    tc_gemm_kernel<64, 256, true, false><<<dim3(gRows, 4), TB>>>(hB, gat2_w, hbuf);
    esed2_kernel<<<esedBlocks, TB>>>(hB, es, ed);
    gat_agg32_kernel<<<aggBlocks, TB>>>(hbuf, es, ed, gat2_b, OUT);
}

// round 16
// speedup vs baseline: 1.9427x; 1.0555x over previous
#include <cuda_runtime.h>
#include <cuda_fp16.h>
#include <math.h>
#include <stdint.h>

#define NN 50000
#define EE 800000
#define E2 (EE + NN)
#define NB ((NN + 255) / 256)
#define BN_EPS 1e-5f

// ---------------- scratch (static __device__, no allocations) ----------------
__device__ int    g_is64;
__device__ int    g_src[EE];
__device__ int    g_dst[EE];
__device__ int    g_deg[NN];
__device__ int    g_bsum[256];
__device__ int    g_rowptr[NN + 1];
__device__ int    g_fill[NN];
__device__ int    g_colsrc[E2];
__device__ float  g_dinv[NN];
__device__ __half g_hA[NN * 64];
__device__ __half g_hB[NN * 64];
__device__ __half g_hbuf[(size_t)NN * 512];   // 51.2 MB fp16 buffer (z / features)
__device__ float  g_es[NN * 8];
__device__ float  g_ed[NN * 8];
__device__ float  g_wcomb[64 * 16];           // [k][o]: o<8 -> W·asrc, o>=8 -> W·adst
__device__ float  g_w2[512 * 64];             // reordered gat1_w for z-GEMM

// ---------------- helpers ----------------
__device__ __forceinline__ float warp_max(float v) {
    #pragma unroll
    for (int o = 16; o; o >>= 1) v = fmaxf(v, __shfl_xor_sync(0xffffffffu, v, o));
    return v;
}
__device__ __forceinline__ float warp_sum(float v) {
    #pragma unroll
    for (int o = 16; o; o >>= 1) v += __shfl_xor_sync(0xffffffffu, v, o);
    return v;
}
__device__ __forceinline__ float lrelu(float x) { return x > 0.f ? x : 0.2f * x; }

// ---------------- graph-structure kernels ----------------
__global__ void detect_kernel(const int* __restrict__ ei) {
    int l = threadIdx.x;
    int any = 0;
    #pragma unroll
    for (int j = 0; j < 32; j++) any |= ei[2 * (j * 32 + l) + 1];
    #pragma unroll
    for (int o = 16; o; o >>= 1) any |= __shfl_xor_sync(0xffffffffu, any, o);
    if (l == 0) g_is64 = (any == 0) ? 1 : 0;
}

__global__ void convert_count_kernel(const void* __restrict__ ei) {
    int e = blockIdx.x * blockDim.x + threadIdx.x;
    if (e >= EE) return;
    int s, d;
    if (g_is64) {
        const long long* p = (const long long*)ei;
        s = (int)p[e];
        d = (int)p[EE + e];
    } else {
        const int* p = (const int*)ei;
        s = p[e];
        d = p[EE + e];
    }
    g_src[e] = s;
    g_dst[e] = d;
    atomicAdd(&g_deg[d], 1);
}

__global__ __launch_bounds__(256) void bsum_kernel() {
    __shared__ int sh[256];
    int t = threadIdx.x;
    int n = blockIdx.x * 256 + t;
    int v = (n < NN) ? (g_deg[n] + 1) : 0;
    sh[t] = v;
    __syncthreads();
    #pragma unroll
    for (int o = 128; o; o >>= 1) {
        if (t < o) sh[t] += sh[t + o];
        __syncthreads();
    }
    if (t == 0) g_bsum[blockIdx.x] = sh[0];
}

// rowptr with block-sum scan folded in.
__global__ __launch_bounds__(256) void rowptr_kernel() {
    __shared__ int sb[256];
    __shared__ int sh[256];
    int t = threadIdx.x;
    int bv = (t < NB) ? g_bsum[t] : 0;
    sb[t] = bv;
    __syncthreads();
    #pragma unroll
    for (int o = 1; o < 256; o <<= 1) {
        int u = (t >= o) ? sb[t - o] : 0;
        __syncthreads();
        sb[t] += u;
        __syncthreads();
    }
    int boff = (blockIdx.x == 0) ? 0 : sb[blockIdx.x - 1];
    int n = blockIdx.x * 256 + t;
    int v = (n < NN) ? (g_deg[n] + 1) : 0;
    sh[t] = v;
    __syncthreads();
    #pragma unroll
    for (int o = 1; o < 256; o <<= 1) {
        int u = (t >= o) ? sh[t - o] : 0;
        __syncthreads();
        sh[t] += u;
        __syncthreads();
    }
    int excl = sh[t] - v + boff;
    if (n < NN) {
        g_rowptr[n] = excl;
        g_fill[n]   = excl;
        g_dinv[n]   = rsqrtf((float)v);
    }
    if (n == NN - 1) g_rowptr[NN] = excl + v;
}

__global__ void fill_kernel() {
    int idx = blockIdx.x * blockDim.x + threadIdx.x;
    if (idx >= E2) return;
    int s, d;
    if (idx < EE) { s = g_src[idx]; d = g_dst[idx]; }
    else          { s = d = idx - EE; }
    int pos = atomicAdd(&g_fill[d], 1);
    g_colsrc[pos] = s;
}

__global__ void sort_kernel() {
    int r = blockIdx.x * blockDim.x + threadIdx.x;
    if (r >= NN) return;
    int s0 = g_rowptr[r], s1 = g_rowptr[r + 1];
    for (int i = s0 + 1; i < s1; i++) {
        int v = g_colsrc[i];
        int j = i - 1;
        while (j >= s0 && g_colsrc[j] > v) { g_colsrc[j + 1] = g_colsrc[j]; j--; }
        g_colsrc[j + 1] = v;
    }
}

// ---------------- tensor-core GEMM: Y[M,NO] = X[M,K] @ W[K,NO] --------------
// EPI: 0 = plain fp16 store; 1 = scale row by g_dinv[row]; 2 = +bias[col], ReLU.
template <int K, int NO, bool HALF_IN, int EPI>
__global__ __launch_bounds__(256) void tc_gemm_kernel(const void* __restrict__ Xv,
                                                      const float* __restrict__ W,
                                                      __half* __restrict__ Y,
                                                      const float* __restrict__ bias) {
    __shared__ __half As[128][72];
    __shared__ __half Bs[64][72];
    int t = threadIdx.x;
    int lane = t & 31, wid = t >> 5;
    int warp_m = wid & 3, warp_n = wid >> 2;
    int rowBase = blockIdx.x * 128;
    int colBase = blockIdx.y * 64;

    float c[2][4][4];
    #pragma unroll
    for (int mt = 0; mt < 2; mt++)
        #pragma unroll
        for (int nt = 0; nt < 4; nt++)
            #pragma unroll
            for (int i = 0; i < 4; i++) c[mt][nt][i] = 0.f;

    for (int kc = 0; kc < K; kc += 64) {
        if (kc) __syncthreads();
        if (HALF_IN) {
            const __half* Xh = (const __half*)Xv;
            #pragma unroll
            for (int i = 0; i < 4; i++) {
                int idx = i * 256 + t;
                int r = idx >> 3, g = idx & 7;
                int row = rowBase + r;
                uint4 u = (row < NN)
                    ? *(const uint4*)(Xh + (size_t)row * K + kc + g * 8)
                    : make_uint4(0u, 0u, 0u, 0u);
                *(uint4*)&As[r][g * 8] = u;
            }
        } else {
            const float* Xf = (const float*)Xv;
            #pragma unroll
            for (int i = 0; i < 8; i++) {
                int idx = i * 256 + t;
                int r = idx >> 4, g = idx & 15;
                int row = rowBase + r;
                float4 f = (row < NN)
                    ? *(const float4*)(Xf + (size_t)row * K + kc + g * 4)
                    : make_float4(0.f, 0.f, 0.f, 0.f);
                *(__half2*)&As[r][g * 4]     = __floats2half2_rn(f.x, f.y);
                *(__half2*)&As[r][g * 4 + 2] = __floats2half2_rn(f.z, f.w);
            }
        }
        #pragma unroll
        for (int i = 0; i < 4; i++) {
            int idx = i * 256 + t;
            int k = idx >> 4, g = idx & 15;
            float4 f = *(const float4*)(W + (size_t)(kc + k) * NO + colBase + g * 4);
            *(__half2*)&Bs[k][g * 4]     = __floats2half2_rn(f.x, f.y);
            *(__half2*)&Bs[k][g * 4 + 2] = __floats2half2_rn(f.z, f.w);
        }
        __syncthreads();
        #pragma unroll
        for (int ks = 0; ks < 4; ks++) {
            uint32_t a[2][4], b[2][4];
            #pragma unroll
            for (int mt = 0; mt < 2; mt++) {
                const __half* p = &As[warp_m * 32 + mt * 16 + (lane & 15)][ks * 16 + (lane >> 4) * 8];
                uint32_t addr = (uint32_t)__cvta_generic_to_shared(p);
                asm volatile("ldmatrix.sync.aligned.m8n8.x4.shared.b16 {%0,%1,%2,%3}, [%4];"
                    : "=r"(a[mt][0]), "=r"(a[mt][1]), "=r"(a[mt][2]), "=r"(a[mt][3])
                    : "r"(addr));
            }
            #pragma unroll
            for (int ng = 0; ng < 2; ng++) {
                const __half* p = &Bs[ks * 16 + (lane & 15)][warp_n * 32 + ng * 16 + (lane >> 4) * 8];
                uint32_t addr = (uint32_t)__cvta_generic_to_shared(p);
                asm volatile("ldmatrix.sync.aligned.m8n8.x4.trans.shared.b16 {%0,%1,%2,%3}, [%4];"
                    : "=r"(b[ng][0]), "=r"(b[ng][1]), "=r"(b[ng][2]), "=r"(b[ng][3])
                    : "r"(addr));
            }
            #pragma unroll
            for (int mt = 0; mt < 2; mt++)
                #pragma unroll
                for (int nt = 0; nt < 4; nt++) {
                    uint32_t b0 = b[nt >> 1][(nt & 1) * 2];
                    uint32_t b1 = b[nt >> 1][(nt & 1) * 2 + 1];
                    asm volatile(
                        "mma.sync.aligned.m16n8k16.row.col.f32.f16.f16.f32 "
                        "{%0,%1,%2,%3}, {%4,%5,%6,%7}, {%8,%9}, {%0,%1,%2,%3};"
                        : "+f"(c[mt][nt][0]), "+f"(c[mt][nt][1]),
                          "+f"(c[mt][nt][2]), "+f"(c[mt][nt][3])
                        : "r"(a[mt][0]), "r"(a[mt][1]), "r"(a[mt][2]), "r"(a[mt][3]),
                          "r"(b0), "r"(b1));
                }
        }
    }
    #pragma unroll
    for (int mt = 0; mt < 2; mt++) {
        int r0 = rowBase + warp_m * 32 + mt * 16 + (lane >> 2);
        float dv0 = 1.f, dv1 = 1.f;
        if (EPI == 1) {
            dv0 = (r0 < NN) ? g_dinv[r0] : 0.f;
            dv1 = (r0 + 8 < NN) ? g_dinv[r0 + 8] : 0.f;
        }
        #pragma unroll
        for (int nt = 0; nt < 4; nt++) {
            int col = colBase + warp_n * 32 + nt * 8 + (lane & 3) * 2;
            float x0 = c[mt][nt][0], x1 = c[mt][nt][1];
            float x2 = c[mt][nt][2], x3 = c[mt][nt][3];
            if (EPI == 1) { x0 *= dv0; x1 *= dv0; x2 *= dv1; x3 *= dv1; }
            if (EPI == 2) {
                float b0 = bias[col], b1 = bias[col + 1];
                x0 = fmaxf(x0 + b0, 0.f); x1 = fmaxf(x1 + b1, 0.f);
                x2 = fmaxf(x2 + b0, 0.f); x3 = fmaxf(x3 + b1, 0.f);
            }
            if (r0 < NN)
                *(__half2*)(Y + (size_t)r0 * NO + col) = __floats2half2_rn(x0, x1);
            if (r0 + 8 < NN)
                *(__half2*)(Y + (size_t)(r0 + 8) * NO + col) = __floats2half2_rn(x2, x3);
        }
    }
}

// ---------------- Wcomb precompute: wcomb[k][o] = sum_c W[k, h*CH+c] * a[h][c]
template <int CH, int NO>
__global__ void wprep_kernel(const float* __restrict__ W,
                             const float* __restrict__ asrc,
                             const float* __restrict__ adst) {
    int t = blockIdx.x * blockDim.x + threadIdx.x;
    if (t >= 1024) return;
    int k = t >> 4, o = t & 15;
    int h = o & 7;
    const float* a = (o < 8) ? asrc : adst;
    float s = 0.f;
    for (int c = 0; c < CH; c++)
        s += W[(size_t)k * NO + h * CH + c] * a[h * CH + c];
    g_wcomb[k * 16 + o] = s;
}

// w2[(h*64+k)*64 + c] = gat1_w[k*512 + h*64 + c]  (reorder for z-GEMM)
__global__ void wprep2_kernel(const float* __restrict__ W) {
    int t = blockIdx.x * blockDim.x + threadIdx.x;
    if (t >= 512 * 64) return;
    int r = t >> 6, c = t & 63;
    int h = r >> 6, k = r & 63;
    g_w2[t] = W[k * 512 + h * 64 + c];
}

// ---------------- es/ed from x (fp16) @ wcomb: warp handles 2 nodes ---------
__global__ __launch_bounds__(256) void esed2_kernel(const __half* __restrict__ x,
                                                    float* __restrict__ es,
                                                    float* __restrict__ ed) {
    __shared__ float sw[1024];
    int t = threadIdx.x;
    for (int i = t; i < 1024; i += 256) sw[i] = g_wcomb[i];
    __syncthreads();
    int warp = (blockIdx.x * 256 + t) >> 5;
    int l = t & 31;
    int n = warp * 2 + (l >> 4);
    int o = l & 15;
    if (n >= NN) return;
    const __half2* xr = (const __half2*)(x + (size_t)n * 64);
    float acc = 0.f;
    #pragma unroll 8
    for (int g = 0; g < 32; g++) {
        float2 f = __half22float2(xr[g]);
        acc += f.x * sw[(2 * g) * 16 + o] + f.y * sw[(2 * g + 1) * 16 + o];
    }
    if (o < 8) es[n * 8 + o] = acc;
    else       ed[n * 8 + (o - 8)] = acc;
}

// ---------------- GCN aggregation (prescaled fp16 in) + BN(eval) + ReLU -----
__global__ __launch_bounds__(256) void gcn_agg_kernel(const __half* __restrict__ h,
                                                      const float* __restrict__ bias,
                                                      const float* __restrict__ gamma,
                                                      const float* __restrict__ beta,
                                                      const float* __restrict__ mean,
                                                      const float* __restrict__ var,
                                                      __half* __restrict__ out) {
    int w = (blockIdx.x * blockDim.x + threadIdx.x) >> 5;
    int l = threadIdx.x & 31;
    if (w >= NN) return;
    int s0 = g_rowptr[w], s1 = g_rowptr[w + 1];
    float a0 = 0.f, a1 = 0.f;
    const __half2* hb = (const __half2*)h;
    for (int i = s0; i < s1; i++) {
        int s = g_colsrc[i];
        float2 v = __half22float2(hb[s * 32 + l]);
        a0 += v.x;
        a1 += v.y;
    }
    float dd = g_dinv[w];
    float2 bi = ((const float2*)bias)[l];
    float2 me = ((const float2*)mean)[l];
    float2 va = ((const float2*)var)[l];
    float2 ga = ((const float2*)gamma)[l];
    float2 be = ((const float2*)beta)[l];
    float v0 = a0 * dd + bi.x;
    float v1 = a1 * dd + bi.y;
    v0 = (v0 - me.x) * rsqrtf(va.x + BN_EPS) * ga.x + be.x;
    v1 = (v1 - me.y) * rsqrtf(va.y + BN_EPS) * ga.y + be.y;
    ((__half2*)(out + (size_t)w * 64))[l] =
        __floats2half2_rn(fmaxf(v0, 0.f), fmaxf(v1, 0.f));
}

// ---------------- GAT1 x-aggregation: z[d, h*64+c] = 0.125/den_h * sum alpha x
// Gathers the 64-dim INPUT x (128B/edge, L2-resident) instead of 8-head
// features. One warp per dst; lane owns channel pair (2l,2l+1); serial walk.
__global__ __launch_bounds__(256) void gat_aggx_kernel(const __half* __restrict__ x,
                                                       const float* __restrict__ es,
                                                       const float* __restrict__ ed,
                                                       __half* __restrict__ z) {
    int d = (blockIdx.x * blockDim.x + threadIdx.x) >> 5;
    int l = threadIdx.x & 31;
    if (d >= NN) return;
    int s0 = g_rowptr[d], s1 = g_rowptr[d + 1];

    float edv = (l < 8) ? ed[d * 8 + l] : 0.f;

    float den = 0.f;
    float acc0[8], acc1[8];
    #pragma unroll
    for (int h = 0; h < 8; h++) { acc0[h] = 0.f; acc1[h] = 0.f; }
    const __half2* xb = (const __half2*)x;
    for (int i = s0; i < s1; i++) {
        int s = g_colsrc[i];
        float wv = 0.f;
        if (l < 8) wv = __expf(lrelu(es[s * 8 + l] + edv));
        den += wv;
        float2 f = __half22float2(xb[s * 32 + l]);
        #pragma unroll
        for (int h = 0; h < 8; h++) {
            float wh = __shfl_sync(0xffffffffu, wv, h);
            acc0[h] += wh * f.x;
            acc1[h] += wh * f.y;
        }
    }
    __half2* zr = (__half2*)(z + (size_t)d * 512);
    #pragma unroll
    for (int h = 0; h < 8; h++) {
        float rd = 0.125f / (__shfl_sync(0xffffffffu, den, h) + 1e-16f);
        zr[h * 32 + l] = __floats2half2_rn(acc0[h] * rd, acc1[h] * rd);
    }
}

// ---------------- GAT-32 aggregation: vectorized + exact log_softmax --------
__global__ __launch_bounds__(256) void gat_agg32_kernel(const __half* __restrict__ hb,
                                                        const float* __restrict__ es,
                                                        const float* __restrict__ ed,
                                                        const float* __restrict__ bias,
                                                        float* __restrict__ out) {
    int d = (blockIdx.x * blockDim.x + threadIdx.x) >> 5;
    int l = threadIdx.x & 31;
    if (d >= NN) return;
    int s0 = g_rowptr[d], s1 = g_rowptr[d + 1];

    float edv = (l < 8) ? ed[d * 8 + l] : 0.f;
    int h0 = l >> 3;

    float den = 0.f;
    float acc[2][4];
    #pragma unroll
    for (int j = 0; j < 2; j++)
        #pragma unroll
        for (int k = 0; k < 4; k++) acc[j][k] = 0.f;

    for (int i = s0; i < s1; i++) {
        int s = g_colsrc[i];
        float wv = 0.f;
        if (l < 8) wv = __expf(lrelu(es[s * 8 + l] + edv));
        den += wv;
        const uint2* hp = (const uint2*)(hb + (size_t)s * 256);
        #pragma unroll
        for (int j = 0; j < 2; j++) {
            float wh = __shfl_sync(0xffffffffu, wv, j * 4 + h0);
            uint2 u = hp[j * 32 + l];
            __half2* hx = (__half2*)&u;
            #pragma unroll
            for (int p = 0; p < 2; p++) {
                float2 f = __half22float2(hx[p]);
                acc[j][2 * p]     += wh * f.x;
                acc[j][2 * p + 1] += wh * f.y;
            }
        }
    }

    float v[4];
    #pragma unroll
    for (int k = 0; k < 4; k++) v[k] = 0.f;
    #pragma unroll
    for (int j = 0; j < 2; j++) {
        float dh = __shfl_sync(0xffffffffu, den, j * 4 + h0);
        float rd = 1.f / (dh + 1e-16f);
        #pragma unroll
        for (int k = 0; k < 4; k++) v[k] += acc[j][k] * rd;
    }
    #pragma unroll
    for (int k = 0; k < 4; k++) {
        v[k] += __shfl_xor_sync(0xffffffffu, v[k], 8);
        v[k] += __shfl_xor_sync(0xffffffffu, v[k], 16);
    }
    {
        float4 bb = *(const float4*)(bias + (l & 7) * 4);
        v[0] = v[0] * 0.125f + bb.x;
        v[1] = v[1] * 0.125f + bb.y;
        v[2] = v[2] * 0.125f + bb.z;
        v[3] = v[3] * 0.125f + bb.w;
    }
    float mx = fmaxf(fmaxf(v[0], v[1]), fmaxf(v[2], v[3]));
    mx = warp_max(mx);
    float se = expf(v[0] - mx) + expf(v[1] - mx) + expf(v[2] - mx) + expf(v[3] - mx);
    se = 0.25f * warp_sum(se);
    float ls = mx + logf(se);
    if (l < 8) {
        float4 o;
        o.x = v[0] - ls; o.y = v[1] - ls; o.z = v[2] - ls; o.w = v[3] - ls;
        *(float4*)(out + (size_t)d * 32 + l * 4) = o;
    }
}

// ---------------- launch ----------------
extern "C" void kernel_launch(void* const* d_in, const int* in_sizes, int n_in,
                              void* d_out, int out_size) {
    const float* X        = (const float*)d_in[0];
    const void*  EI       = d_in[1];
    const float* gcn1_w   = (const float*)d_in[2];
    const float* gcn1_b   = (const float*)d_in[3];
    const float* bn1_g    = (const float*)d_in[4];
    const float* bn1_be   = (const float*)d_in[5];
    const float* bn1_m    = (const float*)d_in[6];
    const float* bn1_v    = (const float*)d_in[7];
    const float* gat1_w   = (const float*)d_in[8];
    const float* gat1_as  = (const float*)d_in[9];
    const float* gat1_ad  = (const float*)d_in[10];
    const float* gat1_b   = (const float*)d_in[11];
    const float* gcn2_w   = (const float*)d_in[12];
    const float* gcn2_b   = (const float*)d_in[13];
    const float* bn2_g    = (const float*)d_in[14];
    const float* bn2_be   = (const float*)d_in[15];
    const float* bn2_m    = (const float*)d_in[16];
    const float* bn2_v    = (const float*)d_in[17];
    const float* gat2_w   = (const float*)d_in[18];
    const float* gat2_as  = (const float*)d_in[19];
    const float* gat2_ad  = (const float*)d_in[20];
    const float* gat2_b   = (const float*)d_in[21];
    float* OUT = (float*)d_out;

    float *es, *ed, *w2;
    __half *hA, *hB, *hbuf;
    int* degPtr;
    cudaGetSymbolAddress((void**)&hA,     g_hA);
    cudaGetSymbolAddress((void**)&hB,     g_hB);
    cudaGetSymbolAddress((void**)&hbuf,   g_hbuf);
    cudaGetSymbolAddress((void**)&es,     g_es);
    cudaGetSymbolAddress((void**)&ed,     g_ed);
    cudaGetSymbolAddress((void**)&w2,     g_w2);
    cudaGetSymbolAddress((void**)&degPtr, g_deg);

    const int TB = 256;
    int gRows      = (NN + 127) / 128;   // 391
    int aggBlocks  = (NN * 32 + TB - 1) / TB;
    int esedBlocks = ((NN + 1) / 2 * 32 + TB - 1) / TB;

    // graph build + weight preps (preps independent, interleaved)
    detect_kernel<<<1, 32>>>((const int*)EI);
    cudaMemsetAsync(degPtr, 0, NN * sizeof(int));
    convert_count_kernel<<<(EE + TB - 1) / TB, TB>>>(EI);
    bsum_kernel<<<NB, 256>>>();
    rowptr_kernel<<<NB, 256>>>();
    fill_kernel<<<(E2 + TB - 1) / TB, TB>>>();
    sort_kernel<<<(NN + TB - 1) / TB, TB>>>();
    wprep2_kernel<<<128, 256>>>(gat1_w);

    // layer 1: GCN -> BN -> ReLU
    tc_gemm_kernel<128, 64, false, 1><<<dim3(gRows, 1), TB>>>(X, gcn1_w, hA, nullptr);
    gcn_agg_kernel<<<aggBlocks, TB>>>(hA, gcn1_b, bn1_g, bn1_be, bn1_m, bn1_v, hB);

    // layer 2: GAT(8 heads, 64 ch, mean) -> ReLU  [aggregate-then-transform]
    wprep_kernel<64, 512><<<4, 256>>>(gat1_w, gat1_as, gat1_ad);
    esed2_kernel<<<esedBlocks, TB>>>(hB, es, ed);
    gat_aggx_kernel<<<aggBlocks, TB>>>(hB, es, ed, hbuf);   // z = [NN,512] fp16
    tc_gemm_kernel<512, 64, true, 2><<<dim3(gRows, 1), TB>>>(hbuf, w2, hA, gat1_b);

    // layer 3: GCN -> BN -> ReLU
    tc_gemm_kernel<64, 64, true, 1><<<dim3(gRows, 1), TB>>>(hA, gcn2_w, hbuf, nullptr);
    gcn_agg_kernel<<<aggBlocks, TB>>>(hbuf, gcn2_b, bn2_g, bn2_be, bn2_m, bn2_v, hB);

    // layer 4: GAT(8 heads, 32 ch, mean) + log_softmax
    wprep_kernel<32, 256><<<4, 256>>>(gat2_w, gat2_as, gat2_ad);
    tc_gemm_kernel<64, 256, true, 0><<<dim3(gRows, 4), TB>>>(hB, gat2_w, hbuf, nullptr);
    esed2_kernel<<<esedBlocks, TB>>>(hB, es, ed);
    gat_agg32_kernel<<<aggBlocks, TB>>>(hbuf, es, ed, gat2_b, OUT);
}

// round 17
// speedup vs baseline: 2.0097x; 1.0345x over previous
#include <cuda_runtime.h>
#include <cuda_fp16.h>
#include <math.h>
#include <stdint.h>

#define NN 50000
#define EE 800000
#define E2 (EE + NN)
#define NB ((NN + 255) / 256)
#define BN_EPS 1e-5f

// ---------------- scratch (static __device__, no allocations) ----------------
__device__ int    g_is64;
__device__ int    g_src[EE];
__device__ int    g_dst[EE];
__device__ int    g_deg[NN];
__device__ int    g_bsum[256];
__device__ int    g_rowptr[NN + 1];
__device__ int    g_fill[NN];
__device__ int    g_colsrc[E2];
__device__ float  g_dinv[NN];
__device__ __half g_hA[NN * 64];
__device__ __half g_hB[NN * 64];
__device__ __half g_hbuf[(size_t)NN * 512];   // 51.2 MB fp16 buffer (z / features)
__device__ float  g_es[NN * 8];
__device__ float  g_ed[NN * 8];
__device__ float  g_wcomb_a[64 * 16];         // layer-2 combined attention weights
__device__ float  g_wcomb_b[64 * 16];         // layer-4 combined attention weights
__device__ float  g_w2[512 * 64];             // reordered gat1_w (k = c*8+h) for z-GEMM

// ---------------- helpers ----------------
__device__ __forceinline__ float warp_max(float v) {
    #pragma unroll
    for (int o = 16; o; o >>= 1) v = fmaxf(v, __shfl_xor_sync(0xffffffffu, v, o));
    return v;
}
__device__ __forceinline__ float warp_sum(float v) {
    #pragma unroll
    for (int o = 16; o; o >>= 1) v += __shfl_xor_sync(0xffffffffu, v, o);
    return v;
}
__device__ __forceinline__ float lrelu(float x) { return x > 0.f ? x : 0.2f * x; }

// ---------------- graph-structure kernels ----------------
// Blocks 0..NB-1 zero deg; block NB probes edge_index dtype (int64 vs int32).
__global__ void init_kernel(const int* __restrict__ ei) {
    if (blockIdx.x < NB) {
        int n = blockIdx.x * 256 + threadIdx.x;
        if (n < NN) g_deg[n] = 0;
    } else {
        __shared__ int bad;
        if (threadIdx.x == 0) bad = 0;
        __syncthreads();
        int any = 0;
        #pragma unroll
        for (int j = 0; j < 4; j++) any |= ei[2 * (j * 256 + threadIdx.x) + 1];
        if (any) atomicOr(&bad, 1);
        __syncthreads();
        if (threadIdx.x == 0) g_is64 = bad ? 0 : 1;
    }
}

__global__ void convert_count_kernel(const void* __restrict__ ei) {
    int e = blockIdx.x * blockDim.x + threadIdx.x;
    if (e >= EE) return;
    int s, d;
    if (g_is64) {
        const long long* p = (const long long*)ei;
        s = (int)p[e];
        d = (int)p[EE + e];
    } else {
        const int* p = (const int*)ei;
        s = p[e];
        d = p[EE + e];
    }
    g_src[e] = s;
    g_dst[e] = d;
    atomicAdd(&g_deg[d], 1);
}

__global__ __launch_bounds__(256) void bsum_kernel() {
    __shared__ int sh[256];
    int t = threadIdx.x;
    int n = blockIdx.x * 256 + t;
    int v = (n < NN) ? (g_deg[n] + 1) : 0;
    sh[t] = v;
    __syncthreads();
    #pragma unroll
    for (int o = 128; o; o >>= 1) {
        if (t < o) sh[t] += sh[t + o];
        __syncthreads();
    }
    if (t == 0) g_bsum[blockIdx.x] = sh[0];
}

// rowptr with block-sum scan folded in.
__global__ __launch_bounds__(256) void rowptr_kernel() {
    __shared__ int sb[256];
    __shared__ int sh[256];
    int t = threadIdx.x;
    int bv = (t < NB) ? g_bsum[t] : 0;
    sb[t] = bv;
    __syncthreads();
    #pragma unroll
    for (int o = 1; o < 256; o <<= 1) {
        int u = (t >= o) ? sb[t - o] : 0;
        __syncthreads();
        sb[t] += u;
        __syncthreads();
    }
    int boff = (blockIdx.x == 0) ? 0 : sb[blockIdx.x - 1];
    int n = blockIdx.x * 256 + t;
    int v = (n < NN) ? (g_deg[n] + 1) : 0;
    sh[t] = v;
    __syncthreads();
    #pragma unroll
    for (int o = 1; o < 256; o <<= 1) {
        int u = (t >= o) ? sh[t - o] : 0;
        __syncthreads();
        sh[t] += u;
        __syncthreads();
    }
    int excl = sh[t] - v + boff;
    if (n < NN) {
        g_rowptr[n] = excl;
        g_fill[n]   = excl;
        g_dinv[n]   = rsqrtf((float)v);
    }
    if (n == NN - 1) g_rowptr[NN] = excl + v;
}

__global__ void fill_kernel() {
    int idx = blockIdx.x * blockDim.x + threadIdx.x;
    if (idx >= E2) return;
    int s, d;
    if (idx < EE) { s = g_src[idx]; d = g_dst[idx]; }
    else          { s = d = idx - EE; }
    int pos = atomicAdd(&g_fill[d], 1);
    g_colsrc[pos] = s;
}

__global__ void sort_kernel() {
    int r = blockIdx.x * blockDim.x + threadIdx.x;
    if (r >= NN) return;
    int s0 = g_rowptr[r], s1 = g_rowptr[r + 1];
    for (int i = s0 + 1; i < s1; i++) {
        int v = g_colsrc[i];
        int j = i - 1;
        while (j >= s0 && g_colsrc[j] > v) { g_colsrc[j + 1] = g_colsrc[j]; j--; }
        g_colsrc[j + 1] = v;
    }
}

// ---------------- merged weight prep -----------------------------------------
// region 0 (t < 32768):        w2[(c*8+h)*64 + cout] = gat1_w[c*512 + h*64 + cout]
// region 1 (next 1024):        wcomb_a from (gat1_w, asrc1, adst1), CH=64, NO=512
// region 2 (next 1024):        wcomb_b from (gat2_w, asrc2, adst2), CH=32, NO=256
__global__ void wprep_all_kernel(const float* __restrict__ w1,
                                 const float* __restrict__ as1,
                                 const float* __restrict__ ad1,
                                 const float* __restrict__ wB,
                                 const float* __restrict__ as2,
                                 const float* __restrict__ ad2) {
    int t = blockIdx.x * blockDim.x + threadIdx.x;
    if (t < 32768) {
        int r = t >> 6, cout = t & 63;
        int c = r >> 3, h = r & 7;
        g_w2[t] = w1[c * 512 + h * 64 + cout];
    } else if (t < 32768 + 1024) {
        int u = t - 32768;
        int k = u >> 4, o = u & 15;
        int h = o & 7;
        const float* a = (o < 8) ? as1 : ad1;
        float s = 0.f;
        for (int c = 0; c < 64; c++)
            s += w1[(size_t)k * 512 + h * 64 + c] * a[h * 64 + c];
        g_wcomb_a[k * 16 + o] = s;
    } else if (t < 32768 + 2048) {
        int u = t - 32768 - 1024;
        int k = u >> 4, o = u & 15;
        int h = o & 7;
        const float* a = (o < 8) ? as2 : ad2;
        float s = 0.f;
        for (int c = 0; c < 32; c++)
            s += wB[(size_t)k * 256 + h * 32 + c] * a[h * 32 + c];
        g_wcomb_b[k * 16 + o] = s;
    }
}

// ---------------- tensor-core GEMM: Y[M,NO] = X[M,K] @ W[K,NO] --------------
// EPI: 0 = plain fp16 store; 1 = scale row by g_dinv[row]; 2 = +bias[col], ReLU.
template <int K, int NO, bool HALF_IN, int EPI>
__global__ __launch_bounds__(256) void tc_gemm_kernel(const void* __restrict__ Xv,
                                                      const float* __restrict__ W,
                                                      __half* __restrict__ Y,
                                                      const float* __restrict__ bias) {
    __shared__ __half As[128][72];
    __shared__ __half Bs[64][72];
    int t = threadIdx.x;
    int lane = t & 31, wid = t >> 5;
    int warp_m = wid & 3, warp_n = wid >> 2;
    int rowBase = blockIdx.x * 128;
    int colBase = blockIdx.y * 64;

    float c[2][4][4];
    #pragma unroll
    for (int mt = 0; mt < 2; mt++)
        #pragma unroll
        for (int nt = 0; nt < 4; nt++)
            #pragma unroll
            for (int i = 0; i < 4; i++) c[mt][nt][i] = 0.f;

    for (int kc = 0; kc < K; kc += 64) {
        if (kc) __syncthreads();
        if (HALF_IN) {
            const __half* Xh = (const __half*)Xv;
            #pragma unroll
            for (int i = 0; i < 4; i++) {
                int idx = i * 256 + t;
                int r = idx >> 3, g = idx & 7;
                int row = rowBase + r;
                uint4 u = (row < NN)
                    ? *(const uint4*)(Xh + (size_t)row * K + kc + g * 8)
                    : make_uint4(0u, 0u, 0u, 0u);
                *(uint4*)&As[r][g * 8] = u;
            }
        } else {
            const float* Xf = (const float*)Xv;
            #pragma unroll
            for (int i = 0; i < 8; i++) {
                int idx = i * 256 + t;
                int r = idx >> 4, g = idx & 15;
                int row = rowBase + r;
                float4 f = (row < NN)
                    ? *(const float4*)(Xf + (size_t)row * K + kc + g * 4)
                    : make_float4(0.f, 0.f, 0.f, 0.f);
                *(__half2*)&As[r][g * 4]     = __floats2half2_rn(f.x, f.y);
                *(__half2*)&As[r][g * 4 + 2] = __floats2half2_rn(f.z, f.w);
            }
        }
        #pragma unroll
        for (int i = 0; i < 4; i++) {
            int idx = i * 256 + t;
            int k = idx >> 4, g = idx & 15;
            float4 f = *(const float4*)(W + (size_t)(kc + k) * NO + colBase + g * 4);
            *(__half2*)&Bs[k][g * 4]     = __floats2half2_rn(f.x, f.y);
            *(__half2*)&Bs[k][g * 4 + 2] = __floats2half2_rn(f.z, f.w);
        }
        __syncthreads();
        #pragma unroll
        for (int ks = 0; ks < 4; ks++) {
            uint32_t a[2][4], b[2][4];
            #pragma unroll
            for (int mt = 0; mt < 2; mt++) {
                const __half* p = &As[warp_m * 32 + mt * 16 + (lane & 15)][ks * 16 + (lane >> 4) * 8];
                uint32_t addr = (uint32_t)__cvta_generic_to_shared(p);
                asm volatile("ldmatrix.sync.aligned.m8n8.x4.shared.b16 {%0,%1,%2,%3}, [%4];"
                    : "=r"(a[mt][0]), "=r"(a[mt][1]), "=r"(a[mt][2]), "=r"(a[mt][3])
                    : "r"(addr));
            }
            #pragma unroll
            for (int ng = 0; ng < 2; ng++) {
                const __half* p = &Bs[ks * 16 + (lane & 15)][warp_n * 32 + ng * 16 + (lane >> 4) * 8];
                uint32_t addr = (uint32_t)__cvta_generic_to_shared(p);
                asm volatile("ldmatrix.sync.aligned.m8n8.x4.trans.shared.b16 {%0,%1,%2,%3}, [%4];"
                    : "=r"(b[ng][0]), "=r"(b[ng][1]), "=r"(b[ng][2]), "=r"(b[ng][3])
                    : "r"(addr));
            }
            #pragma unroll
            for (int mt = 0; mt < 2; mt++)
                #pragma unroll
                for (int nt = 0; nt < 4; nt++) {
                    uint32_t b0 = b[nt >> 1][(nt & 1) * 2];
                    uint32_t b1 = b[nt >> 1][(nt & 1) * 2 + 1];
                    asm volatile(
                        "mma.sync.aligned.m16n8k16.row.col.f32.f16.f16.f32 "
                        "{%0,%1,%2,%3}, {%4,%5,%6,%7}, {%8,%9}, {%0,%1,%2,%3};"
                        : "+f"(c[mt][nt][0]), "+f"(c[mt][nt][1]),
                          "+f"(c[mt][nt][2]), "+f"(c[mt][nt][3])
                        : "r"(a[mt][0]), "r"(a[mt][1]), "r"(a[mt][2]), "r"(a[mt][3]),
                          "r"(b0), "r"(b1));
                }
        }
    }
    #pragma unroll
    for (int mt = 0; mt < 2; mt++) {
        int r0 = rowBase + warp_m * 32 + mt * 16 + (lane >> 2);
        float dv0 = 1.f, dv1 = 1.f;
        if (EPI == 1) {
            dv0 = (r0 < NN) ? g_dinv[r0] : 0.f;
            dv1 = (r0 + 8 < NN) ? g_dinv[r0 + 8] : 0.f;
        }
        #pragma unroll
        for (int nt = 0; nt < 4; nt++) {
            int col = colBase + warp_n * 32 + nt * 8 + (lane & 3) * 2;
            float x0 = c[mt][nt][0], x1 = c[mt][nt][1];
            float x2 = c[mt][nt][2], x3 = c[mt][nt][3];
            if (EPI == 1) { x0 *= dv0; x1 *= dv0; x2 *= dv1; x3 *= dv1; }
            if (EPI == 2) {
                float b0 = bias[col], b1 = bias[col + 1];
                x0 = fmaxf(x0 + b0, 0.f); x1 = fmaxf(x1 + b1, 0.f);
                x2 = fmaxf(x2 + b0, 0.f); x3 = fmaxf(x3 + b1, 0.f);
            }
            if (r0 < NN)
                *(__half2*)(Y + (size_t)r0 * NO + col) = __floats2half2_rn(x0, x1);
            if (r0 + 8 < NN)
                *(__half2*)(Y + (size_t)(r0 + 8) * NO + col) = __floats2half2_rn(x2, x3);
        }
    }
}

// ---------------- es/ed from x (fp16) @ wcomb: warp handles 2 nodes ---------
__global__ __launch_bounds__(256) void esed2_kernel(const __half* __restrict__ x,
                                                    const float* __restrict__ wc,
                                                    float* __restrict__ es,
                                                    float* __restrict__ ed) {
    __shared__ float sw[1024];
    int t = threadIdx.x;
    for (int i = t; i < 1024; i += 256) sw[i] = wc[i];
    __syncthreads();
    int warp = (blockIdx.x * 256 + t) >> 5;
    int l = t & 31;
    int n = warp * 2 + (l >> 4);
    int o = l & 15;
    if (n >= NN) return;
    const __half2* xr = (const __half2*)(x + (size_t)n * 64);
    float acc = 0.f;
    #pragma unroll 8
    for (int g = 0; g < 32; g++) {
        float2 f = __half22float2(xr[g]);
        acc += f.x * sw[(2 * g) * 16 + o] + f.y * sw[(2 * g + 1) * 16 + o];
    }
    if (o < 8) es[n * 8 + o] = acc;
    else       ed[n * 8 + (o - 8)] = acc;
}

// ---------------- GCN aggregation (prescaled fp16 in) + BN(eval) + ReLU -----
__global__ __launch_bounds__(256) void gcn_agg_kernel(const __half* __restrict__ h,
                                                      const float* __restrict__ bias,
                                                      const float* __restrict__ gamma,
                                                      const float* __restrict__ beta,
                                                      const float* __restrict__ mean,
                                                      const float* __restrict__ var,
                                                      __half* __restrict__ out) {
    int w = (blockIdx.x * blockDim.x + threadIdx.x) >> 5;
    int l = threadIdx.x & 31;
    if (w >= NN) return;
    int s0 = g_rowptr[w], s1 = g_rowptr[w + 1];
    float a0 = 0.f, a1 = 0.f;
    const __half2* hb = (const __half2*)h;
    for (int i = s0; i < s1; i++) {
        int s = g_colsrc[i];
        float2 v = __half22float2(hb[s * 32 + l]);
        a0 += v.x;
        a1 += v.y;
    }
    float dd = g_dinv[w];
    float2 bi = ((const float2*)bias)[l];
    float2 me = ((const float2*)mean)[l];
    float2 va = ((const float2*)var)[l];
    float2 ga = ((const float2*)gamma)[l];
    float2 be = ((const float2*)beta)[l];
    float v0 = a0 * dd + bi.x;
    float v1 = a1 * dd + bi.y;
    v0 = (v0 - me.x) * rsqrtf(va.x + BN_EPS) * ga.x + be.x;
    v1 = (v1 - me.y) * rsqrtf(va.y + BN_EPS) * ga.y + be.y;
    ((__half2*)(out + (size_t)w * 64))[l] =
        __floats2half2_rn(fmaxf(v0, 0.f), fmaxf(v1, 0.f));
}

// ---------------- GAT1 x-aggregation, channel-major z (k = c*8+h) -----------
// z[d*512 + 16l + h]     = 0.125/den_h * acc0[h]   (channel 2l)
// z[d*512 + 16l + 8 + h] = 0.125/den_h * acc1[h]   (channel 2l+1)
// Lane's 16 halves contiguous -> 2x STG.128, fully coalesced across warp.
__global__ __launch_bounds__(256) void gat_aggx_kernel(const __half* __restrict__ x,
                                                       const float* __restrict__ es,
                                                       const float* __restrict__ ed,
                                                       __half* __restrict__ z) {
    int d = (blockIdx.x * blockDim.x + threadIdx.x) >> 5;
    int l = threadIdx.x & 31;
    if (d >= NN) return;
    int s0 = g_rowptr[d], s1 = g_rowptr[d + 1];

    float edv = (l < 8) ? ed[d * 8 + l] : 0.f;

    float den = 0.f;
    float acc0[8], acc1[8];
    #pragma unroll
    for (int h = 0; h < 8; h++) { acc0[h] = 0.f; acc1[h] = 0.f; }
    const __half2* xb = (const __half2*)x;
    for (int i = s0; i < s1; i++) {
        int s = g_colsrc[i];
        float wv = 0.f;
        if (l < 8) wv = __expf(lrelu(es[s * 8 + l] + edv));
        den += wv;
        float2 f = __half22float2(xb[s * 32 + l]);
        #pragma unroll
        for (int h = 0; h < 8; h++) {
            float wh = __shfl_sync(0xffffffffu, wv, h);
            acc0[h] += wh * f.x;
            acc1[h] += wh * f.y;
        }
    }
    float a0r[8], a1r[8];
    #pragma unroll
    for (int h = 0; h < 8; h++) {
        float rd = 0.125f / (__shfl_sync(0xffffffffu, den, h) + 1e-16f);
        a0r[h] = acc0[h] * rd;
        a1r[h] = acc1[h] * rd;
    }
    uint4 u0, u1;
    {
        __half2 p;
        p = __floats2half2_rn(a0r[0], a0r[1]); u0.x = *(uint32_t*)&p;
        p = __floats2half2_rn(a0r[2], a0r[3]); u0.y = *(uint32_t*)&p;
        p = __floats2half2_rn(a0r[4], a0r[5]); u0.z = *(uint32_t*)&p;
        p = __floats2half2_rn(a0r[6], a0r[7]); u0.w = *(uint32_t*)&p;
        p = __floats2half2_rn(a1r[0], a1r[1]); u1.x = *(uint32_t*)&p;
        p = __floats2half2_rn(a1r[2], a1r[3]); u1.y = *(uint32_t*)&p;
        p = __floats2half2_rn(a1r[4], a1r[5]); u1.z = *(uint32_t*)&p;
        p = __floats2half2_rn(a1r[6], a1r[7]); u1.w = *(uint32_t*)&p;
    }
    *(uint4*)(z + (size_t)d * 512 + 16 * l)     = u0;
    *(uint4*)(z + (size_t)d * 512 + 16 * l + 8) = u1;
}

// ---------------- GAT-32 aggregation: vectorized + exact log_softmax --------
__global__ __launch_bounds__(256) void gat_agg32_kernel(const __half* __restrict__ hb,
                                                        const float* __restrict__ es,
                                                        const float* __restrict__ ed,
                                                        const float* __restrict__ bias,
                                                        float* __restrict__ out) {
    int d = (blockIdx.x * blockDim.x + threadIdx.x) >> 5;
    int l = threadIdx.x & 31;
    if (d >= NN) return;
    int s0 = g_rowptr[d], s1 = g_rowptr[d + 1];

    float edv = (l < 8) ? ed[d * 8 + l] : 0.f;
    int h0 = l >> 3;

    float den = 0.f;
    float acc[2][4];
    #pragma unroll
    for (int j = 0; j < 2; j++)
        #pragma unroll
        for (int k = 0; k < 4; k++) acc[j][k] = 0.f;

    for (int i = s0; i < s1; i++) {
        int s = g_colsrc[i];
        float wv = 0.f;
        if (l < 8) wv = __expf(lrelu(es[s * 8 + l] + edv));
        den += wv;
        const uint2* hp = (const uint2*)(hb + (size_t)s * 256);
        #pragma unroll
        for (int j = 0; j < 2; j++) {
            float wh = __shfl_sync(0xffffffffu, wv, j * 4 + h0);
            uint2 u = hp[j * 32 + l];
            __half2* hx = (__half2*)&u;
            #pragma unroll
            for (int p = 0; p < 2; p++) {
                float2 f = __half22float2(hx[p]);
                acc[j][2 * p]     += wh * f.x;
                acc[j][2 * p + 1] += wh * f.y;
            }
        }
    }

    float v[4];
    #pragma unroll
    for (int k = 0; k < 4; k++) v[k] = 0.f;
    #pragma unroll
    for (int j = 0; j < 2; j++) {
        float dh = __shfl_sync(0xffffffffu, den, j * 4 + h0);
        float rd = 1.f / (dh + 1e-16f);
        #pragma unroll
        for (int k = 0; k < 4; k++) v[k] += acc[j][k] * rd;
    }
    #pragma unroll
    for (int k = 0; k < 4; k++) {
        v[k] += __shfl_xor_sync(0xffffffffu, v[k], 8);
        v[k] += __shfl_xor_sync(0xffffffffu, v[k], 16);
    }
    {
        float4 bb = *(const float4*)(bias + (l & 7) * 4);
        v[0] = v[0] * 0.125f + bb.x;
        v[1] = v[1] * 0.125f + bb.y;
        v[2] = v[2] * 0.125f + bb.z;
        v[3] = v[3] * 0.125f + bb.w;
    }
    float mx = fmaxf(fmaxf(v[0], v[1]), fmaxf(v[2], v[3]));
    mx = warp_max(mx);
    float se = expf(v[0] - mx) + expf(v[1] - mx) + expf(v[2] - mx) + expf(v[3] - mx);
    se = 0.25f * warp_sum(se);
    float ls = mx + logf(se);
    if (l < 8) {
        float4 o;
        o.x = v[0] - ls; o.y = v[1] - ls; o.z = v[2] - ls; o.w = v[3] - ls;
        *(float4*)(out + (size_t)d * 32 + l * 4) = o;
    }
}

// ---------------- launch ----------------
extern "C" void kernel_launch(void* const* d_in, const int* in_sizes, int n_in,
                              void* d_out, int out_size) {
    const float* X        = (const float*)d_in[0];
    const void*  EI       = d_in[1];
    const float* gcn1_w   = (const float*)d_in[2];
    const float* gcn1_b   = (const float*)d_in[3];
    const float* bn1_g    = (const float*)d_in[4];
    const float* bn1_be   = (const float*)d_in[5];
    const float* bn1_m    = (const float*)d_in[6];
    const float* bn1_v    = (const float*)d_in[7];
    const float* gat1_w   = (const float*)d_in[8];
    const float* gat1_as  = (const float*)d_in[9];
    const float* gat1_ad  = (const float*)d_in[10];
    const float* gat1_b   = (const float*)d_in[11];
    const float* gcn2_w   = (const float*)d_in[12];
    const float* gcn2_b   = (const float*)d_in[13];
    const float* bn2_g    = (const float*)d_in[14];
    const float* bn2_be   = (const float*)d_in[15];
    const float* bn2_m    = (const float*)d_in[16];
    const float* bn2_v    = (const float*)d_in[17];
    const float* gat2_w   = (const float*)d_in[18];
    const float* gat2_as  = (const float*)d_in[19];
    const float* gat2_ad  = (const float*)d_in[20];
    const float* gat2_b   = (const float*)d_in[21];
    float* OUT = (float*)d_out;

    float *es, *ed, *w2, *wca, *wcb;
    __half *hA, *hB, *hbuf;
    cudaGetSymbolAddress((void**)&hA,   g_hA);
    cudaGetSymbolAddress((void**)&hB,   g_hB);
    cudaGetSymbolAddress((void**)&hbuf, g_hbuf);
    cudaGetSymbolAddress((void**)&es,   g_es);
    cudaGetSymbolAddress((void**)&ed,   g_ed);
    cudaGetSymbolAddress((void**)&w2,   g_w2);
    cudaGetSymbolAddress((void**)&wca,  g_wcomb_a);
    cudaGetSymbolAddress((void**)&wcb,  g_wcomb_b);

    const int TB = 256;
    int gRows      = (NN + 127) / 128;   // 391
    int aggBlocks  = (NN * 32 + TB - 1) / TB;
    int esedBlocks = ((NN + 1) / 2 * 32 + TB - 1) / TB;

    // graph build + weight prep
    init_kernel<<<NB + 1, 256>>>((const int*)EI);                         // 1
    convert_count_kernel<<<(EE + TB - 1) / TB, TB>>>(EI);                 // 2
    bsum_kernel<<<NB, 256>>>();                                           // 3
    rowptr_kernel<<<NB, 256>>>();                                         // 4
    fill_kernel<<<(E2 + TB - 1) / TB, TB>>>();                            // 5 <- profiled
    sort_kernel<<<(NN + TB - 1) / TB, TB>>>();
    wprep_all_kernel<<<(32768 + 2048 + 255) / 256, 256>>>(gat1_w, gat1_as, gat1_ad,
                                                          gat2_w, gat2_as, gat2_ad);

    // layer 1: GCN -> BN -> ReLU
    tc_gemm_kernel<128, 64, false, 1><<<dim3(gRows, 1), TB>>>(X, gcn1_w, hA, nullptr);
    gcn_agg_kernel<<<aggBlocks, TB>>>(hA, gcn1_b, bn1_g, bn1_be, bn1_m, bn1_v, hB);

    // layer 2: GAT(8 heads, 64 ch, mean) -> ReLU  [aggregate-then-transform]
    esed2_kernel<<<esedBlocks, TB>>>(hB, wca, es, ed);
    gat_aggx_kernel<<<aggBlocks, TB>>>(hB, es, ed, hbuf);   // z = [NN,512] fp16
    tc_gemm_kernel<512, 64, true, 2><<<dim3(gRows, 1), TB>>>(hbuf, w2, hA, gat1_b);

    // layer 3: GCN -> BN -> ReLU
    tc_gemm_kernel<64, 64, true, 1><<<dim3(gRows, 1), TB>>>(hA, gcn2_w, hbuf, nullptr);
    gcn_agg_kernel<<<aggBlocks, TB>>>(hbuf, gcn2_b, bn2_g, bn2_be, bn2_m, bn2_v, hB);

    // layer 4: GAT(8 heads, 32 ch, mean) + log_softmax
    tc_gemm_kernel<64, 256, true, 0><<<dim3(gRows, 4), TB>>>(hB, gat2_w, hbuf, nullptr);
    esed2_kernel<<<esedBlocks, TB>>>(hB, wcb, es, ed);
    gat_agg32_kernel<<<aggBlocks, TB>>>(hbuf, es, ed, gat2_b, OUT);
}